// round 13
// baseline (speedup 1.0000x reference)
#include <cuda_runtime.h>
#include <cuda_fp16.h>
#include <cstdint>

#define T_LEN 4096
#define E_DIM 1024
#define H_NUM 16
#define HD    64
#define NBX_SCORES 4     // column splits in scores kernel
#define NT_SC 8          // K-tiles per scores block

// Scratch (allocation-free rule: __device__ globals)
__device__ __half g_Q  [(long)H_NUM * T_LEN * HD];
__device__ __half g_K  [(long)H_NUM * T_LEN * HD];
__device__ __half g_Vt [(long)H_NUM * HD * T_LEN];
__device__ __half g_P  [(long)H_NUM * T_LEN * T_LEN];
__device__ __half g_CTX[(long)T_LEN * E_DIM];
__device__ __half g_X16[(long)3 * T_LEN * E_DIM];        // fp16 q_in|k_in|v_in
__device__ __half g_W16[(long)4 * E_DIM * E_DIM];        // fp16 wq|wk|wv|ow
__device__ float  g_RSP[(long)H_NUM * T_LEN * NBX_SCORES];
__device__ float  g_INV[(long)H_NUM * T_LEN];

__device__ __forceinline__ float ex2(float x) {
    float r;
    asm("ex2.approx.f32 %0, %1;" : "=f"(r) : "f"(x));
    return r;
}
__device__ __forceinline__ uint32_t smem_u32(const void* p) {
    return (uint32_t)__cvta_generic_to_shared(p);
}
__device__ __forceinline__ void ldsm_x4(uint32_t r[4], uint32_t addr) {
    asm volatile("ldmatrix.sync.aligned.m8n8.x4.shared.b16 {%0,%1,%2,%3}, [%4];"
        : "=r"(r[0]), "=r"(r[1]), "=r"(r[2]), "=r"(r[3]) : "r"(addr));
}
__device__ __forceinline__ void cp_async16(uint32_t saddr, const void* gaddr) {
    asm volatile("cp.async.cg.shared.global [%0], [%1], 16;" :: "r"(saddr), "l"(gaddr));
}
__device__ __forceinline__ void cp_commit() { asm volatile("cp.async.commit_group;"); }
template<int N>
__device__ __forceinline__ void cp_wait() {
    asm volatile("cp.async.wait_group %0;" :: "n"(N));
}

__device__ __forceinline__ void mma_f16(float c[4],
    uint32_t a0, uint32_t a1, uint32_t a2, uint32_t a3,
    uint32_t b0, uint32_t b1)
{
    asm volatile(
        "mma.sync.aligned.m16n8k16.row.col.f32.f16.f16.f32 "
        "{%0,%1,%2,%3}, {%4,%5,%6,%7}, {%8,%9}, {%0,%1,%2,%3};"
        : "+f"(c[0]), "+f"(c[1]), "+f"(c[2]), "+f"(c[3])
        : "r"(a0), "r"(a1), "r"(a2), "r"(a3), "r"(b0), "r"(b1));
}

#define LOG2E 1.4426950408889634f
#define PSHIFT 2.0f

// ---------------------------------------------------------------------------
// fp32 -> fp16 bulk convert
// ---------------------------------------------------------------------------
__global__ __launch_bounds__(256) void cvt_k(const float* __restrict__ src,
                                             __half* __restrict__ dst)
{
    const long i = ((long)blockIdx.x * 256 + threadIdx.x) * 4;
    float4 t = *(const float4*)(src + i);
    *(__half2*)(dst + i)     = __floats2half2_rn(t.x, t.y);
    *(__half2*)(dst + i + 2) = __floats2half2_rn(t.z, t.w);
}

// ===========================================================================
// Scores (R12 version, unchanged): 2-stage cp.async, Q frags in regs,
// STG.128 epilogue via quad transpose.
// ===========================================================================
__global__ __launch_bounds__(256, 2)
void scores_k(const __half* __restrict__ Q, const __half* __restrict__ Kp,
              __half* __restrict__ P, float* __restrict__ rsp)
{
    __shared__ __half Qs[128][72];
    __shared__ __half Ks[2][128][72];
    __shared__ float  srs[512];

    const int tid  = threadIdx.x;
    const int warp = tid >> 5, lane = tid & 31;
    const int gid = lane >> 2, tg = lane & 3;
    const int wm0 = (warp >> 2) * 64;
    const int wn0 = (warp & 3) * 32;
    const int gm0 = blockIdx.y * 128;
    const int cbase = blockIdx.x * (NT_SC * 128);

    const __half* Ah = Q  + (long)blockIdx.z * T_LEN * HD + (long)gm0 * HD;
    const __half* Kh = Kp + (long)blockIdx.z * T_LEN * HD + (long)cbase * HD;

    int lm[4], lk[4];
#pragma unroll
    for (int i = 0; i < 4; i++) {
        const int idx = (tid + i * 256) * 8;
        lm[i] = idx >> 6; lk[i] = idx & 63;
    }
    auto prefetchK = [&](int nt, int buf) {
#pragma unroll
        for (int i = 0; i < 4; i++)
            cp_async16(smem_u32(&Ks[buf][lm[i]][lk[i]]),
                       Kh + ((long)nt * 128 + lm[i]) * HD + lk[i]);
    };

#pragma unroll
    for (int i = 0; i < 4; i++)
        cp_async16(smem_u32(&Qs[lm[i]][lk[i]]), Ah + (long)lm[i] * HD + lk[i]);
    prefetchK(0, 0); cp_commit();
    prefetchK(1, 1); cp_commit();
    cp_wait<1>();
    __syncthreads();

    uint32_t af[4][4][4];
#pragma unroll
    for (int i = 0; i < 4; i++) {
        const uint32_t a = smem_u32(&Qs[wm0 + i*16 + (lane & 15)][(lane >> 4) * 8]);
#pragma unroll
        for (int ks = 0; ks < 4; ks++) ldsm_x4(af[ks][i], a + ks * 32);
    }

    uint32_t bAddr[2][2];
#pragma unroll
    for (int buf = 0; buf < 2; buf++)
#pragma unroll
        for (int jp = 0; jp < 2; jp++)
            bAddr[buf][jp] = smem_u32(
                &Ks[buf][wn0 + jp*16 + (lane & 7) + ((lane >> 4) << 3)]
                        [((lane >> 3) & 1) * 8]);

    float rsum[4][2];
#pragma unroll
    for (int i = 0; i < 4; i++) { rsum[i][0] = 0.f; rsum[i][1] = 0.f; }

    __half* Ch = P + (long)blockIdx.z * T_LEN * T_LEN;

#pragma unroll 1
    for (int nt = 0; nt < NT_SC; nt++) {
        const int buf = nt & 1;

        float acc[4][4][4];
#pragma unroll
        for (int i = 0; i < 4; i++)
#pragma unroll
            for (int j = 0; j < 4; j++)
#pragma unroll
                for (int q = 0; q < 4; q++) acc[i][j][q] = 0.0f;

#pragma unroll
        for (int ks = 0; ks < 4; ks++) {
            uint32_t bq[2][4];
#pragma unroll
            for (int jp = 0; jp < 2; jp++)
                ldsm_x4(bq[jp], bAddr[buf][jp] + ks * 32);
#pragma unroll
            for (int i = 0; i < 4; i++)
#pragma unroll
                for (int j = 0; j < 4; j++)
                    mma_f16(acc[i][j], af[ks][i][0], af[ks][i][1],
                            af[ks][i][2], af[ks][i][3],
                            bq[j >> 1][(j & 1) * 2], bq[j >> 1][(j & 1) * 2 + 1]);
        }

        const int n0t = cbase + nt * 128;
#pragma unroll
        for (int i = 0; i < 4; i++) {
#pragma unroll
            for (int h2 = 0; h2 < 2; h2++) {
                uint32_t hp[4];
#pragma unroll
                for (int j = 0; j < 4; j++) {
                    float v0 = ex2(fmaf(acc[i][j][h2*2 + 0], LOG2E, PSHIFT));
                    float v1 = ex2(fmaf(acc[i][j][h2*2 + 1], LOG2E, PSHIFT));
                    rsum[i][h2] += v0 + v1;
                    __half2 h = __floats2half2_rn(v0, v1);
                    hp[j] = *(uint32_t*)&h;
                }
                {
                    uint32_t t, r;
                    t = (tg & 1) ? hp[0] : hp[1];
                    r = __shfl_xor_sync(0xffffffffu, t, 1);
                    if (tg & 1) hp[0] = r; else hp[1] = r;
                    t = (tg & 1) ? hp[2] : hp[3];
                    r = __shfl_xor_sync(0xffffffffu, t, 1);
                    if (tg & 1) hp[2] = r; else hp[3] = r;
                    t = (tg & 2) ? hp[0] : hp[2];
                    r = __shfl_xor_sync(0xffffffffu, t, 2);
                    if (tg & 2) hp[0] = r; else hp[2] = r;
                    t = (tg & 2) ? hp[1] : hp[3];
                    r = __shfl_xor_sync(0xffffffffu, t, 2);
                    if (tg & 2) hp[1] = r; else hp[3] = r;
                }
                const int m = gm0 + wm0 + i * 16 + gid + h2 * 8;
                const int n = n0t + wn0 + tg * 8;
                *(uint4*)(Ch + (long)m * T_LEN + n) =
                    make_uint4(hp[0], hp[1], hp[2], hp[3]);
            }
        }

        __syncthreads();
        if (nt + 2 < NT_SC) { prefetchK(nt + 2, buf); cp_commit(); }
        if (nt + 1 < NT_SC) {
            if (nt + 2 < NT_SC) cp_wait<1>(); else cp_wait<0>();
            __syncthreads();
        }
    }

#pragma unroll
    for (int i = 0; i < 4; i++)
#pragma unroll
        for (int h2 = 0; h2 < 2; h2++)
#pragma unroll
            for (int o = 1; o < 4; o <<= 1)
                rsum[i][h2] += __shfl_xor_sync(0xffffffffu, rsum[i][h2], o);
    if (tg == 0) {
        const int wn = warp & 3;
#pragma unroll
        for (int i = 0; i < 4; i++)
#pragma unroll
            for (int h2 = 0; h2 < 2; h2++)
                srs[wn * 128 + wm0 + i * 16 + h2 * 8 + gid] = rsum[i][h2];
    }
    __syncthreads();
    if (tid < 128) {
        float s = srs[tid] + srs[128 + tid] + srs[256 + tid] + srs[384 + tid];
        rsp[((long)blockIdx.z * T_LEN + gm0 + tid) * NBX_SCORES + blockIdx.x] = s;
    }
}

// ===========================================================================
// Dedicated ctx kernel (R11, unchanged).
// ===========================================================================
#define CTX_BK 64
#define CTX_NI (T_LEN / CTX_BK)   // 64

__global__ __launch_bounds__(256, 2)
void ctx_k(const __half* __restrict__ P, const __half* __restrict__ Vt,
           const float* __restrict__ inv, __half* __restrict__ CTX)
{
    __shared__ __half Ps[3][128][72];
    __shared__ __half Vs[3][64][72];

    const int tid  = threadIdx.x;
    const int warp = tid >> 5, lane = tid & 31;
    const int gid = lane >> 2, tg = lane & 3;
    const int wm0 = (warp >> 1) * 32;
    const int wn0 = (warp & 1) * 32;
    const int gm0 = blockIdx.x * 128;
    const int h   = blockIdx.y;

    const __half* Ph = P  + (long)h * T_LEN * T_LEN + (long)gm0 * T_LEN;
    const __half* Vh = Vt + (long)h * HD * T_LEN;

    int am[4], ak[4], bd[2], bk[2];
#pragma unroll
    for (int i = 0; i < 4; i++) {
        const int idx = (tid + i * 256) * 8;
        am[i] = idx >> 6; ak[i] = idx & 63;
    }
#pragma unroll
    for (int i = 0; i < 2; i++) {
        const int idx = (tid + i * 256) * 8;
        bd[i] = idx >> 6; bk[i] = idx & 63;
    }

    auto prefetch = [&](int it, int buf) {
        const int s0 = it * CTX_BK;
#pragma unroll
        for (int i = 0; i < 4; i++)
            cp_async16(smem_u32(&Ps[buf][am[i]][ak[i]]),
                       Ph + (long)am[i] * T_LEN + s0 + ak[i]);
#pragma unroll
        for (int i = 0; i < 2; i++)
            cp_async16(smem_u32(&Vs[buf][bd[i]][bk[i]]),
                       Vh + (long)bd[i] * T_LEN + s0 + bk[i]);
    };

    prefetch(0, 0); cp_commit();
    prefetch(1, 1); cp_commit();
    prefetch(2, 2); cp_commit();
    cp_wait<2>();
    __syncthreads();

    uint32_t aAddr[3][2], bAddr[3][2];
#pragma unroll
    for (int st = 0; st < 3; st++) {
#pragma unroll
        for (int i = 0; i < 2; i++)
            aAddr[st][i] = smem_u32(
                &Ps[st][wm0 + i*16 + (lane & 15)][(lane >> 4) * 8]);
#pragma unroll
        for (int jp = 0; jp < 2; jp++)
            bAddr[st][jp] = smem_u32(
                &Vs[st][wn0 + jp*16 + (lane & 7) + ((lane >> 4) << 3)]
                       [((lane >> 3) & 1) * 8]);
    }

    float acc[2][4][4];
#pragma unroll
    for (int i = 0; i < 2; i++)
#pragma unroll
        for (int j = 0; j < 4; j++)
#pragma unroll
            for (int q = 0; q < 4; q++) acc[i][j][q] = 0.0f;

#pragma unroll 1
    for (int it = 0; it < CTX_NI; ++it) {
        const int buf = it % 3;
#pragma unroll
        for (int ks = 0; ks < 4; ks++) {
            uint32_t af[2][4], bq[2][4];
#pragma unroll
            for (int i = 0; i < 2; i++) ldsm_x4(af[i], aAddr[buf][i] + ks * 32);
#pragma unroll
            for (int jp = 0; jp < 2; jp++) ldsm_x4(bq[jp], bAddr[buf][jp] + ks * 32);
#pragma unroll
            for (int i = 0; i < 2; i++)
#pragma unroll
                for (int j = 0; j < 4; j++)
                    mma_f16(acc[i][j], af[i][0], af[i][1], af[i][2], af[i][3],
                            bq[j >> 1][(j & 1) * 2], bq[j >> 1][(j & 1) * 2 + 1]);
        }
        __syncthreads();
        if (it + 3 < CTX_NI) { prefetch(it + 3, buf); cp_commit(); }
        if (it + 1 < CTX_NI) {
            if (it + 3 < CTX_NI)       cp_wait<2>();
            else if (it + 2 < CTX_NI)  cp_wait<1>();
            else                       cp_wait<0>();
            __syncthreads();
        }
    }

    const float* invh = inv + (long)h * T_LEN;
#pragma unroll
    for (int i = 0; i < 2; i++) {
#pragma unroll
        for (int j = 0; j < 4; j++) {
#pragma unroll
            for (int h2 = 0; h2 < 2; h2++) {
                const int m = gm0 + wm0 + i*16 + gid + h2*8;
                const int n = h * HD + wn0 + j*8 + tg*2;
                const float sc = invh[m];
                float v0 = acc[i][j][h2*2 + 0] * sc;
                float v1 = acc[i][j][h2*2 + 1] * sc;
                *(__half2*)(CTX + (long)m * E_DIM + n) = __floats2half2_rn(v0, v1);
            }
        }
    }
}

// ===========================================================================
// All-fp16 GEMM, 3-stage cp.async pipeline, BM=BN=128, BK=32, 256 thr (2x4).
//   C = (A @ B^T + bias) * scale
//   EPI 0: fp32 C[m*ldc+n]; 1: fp16 head-scatter [h][m][d]; 2: fp16 [h][d][m]
// ===========================================================================
template<int EPI>
__global__ __launch_bounds__(256, 2)
void gemm16_k(const __half* __restrict__ A, const __half* __restrict__ B,
              const float* __restrict__ bias, void* __restrict__ Cv,
              int M, int N, int K, int ldc, float scale)
{
    constexpr int BK = 32;
    __shared__ __half As[3][128][40];
    __shared__ __half Bs[3][128][40];
    constexpr uint32_t A_BUF = 128 * 40 * 2;
    constexpr uint32_t B_BUF = 128 * 40 * 2;

    const int tid  = threadIdx.x;
    const int warp = tid >> 5, lane = tid & 31;
    const int wm0 = (warp >> 2) * 64;   // WARPS_M=2 -> WM=64, MT=4
    const int wn0 = (warp & 3) * 32;    // WARPS_N=4 -> WN=32, NT=4
    const int gid = lane >> 2, tg = lane & 3;
    const int gm0 = blockIdx.y * 128, gn0 = blockIdx.x * 128;

    // 128x32 halfs per tile = 512 16B-chunks -> 2 per thread
    int am[2], ak[2];
#pragma unroll
    for (int i = 0; i < 2; i++) {
        const int idx = (tid + i * 256) * 8;
        am[i] = idx >> 5; ak[i] = idx & 31;
    }

    auto prefetch = [&](int it, int buf) {
        const int k0 = it * BK;
#pragma unroll
        for (int i = 0; i < 2; i++)
            cp_async16(smem_u32(&As[buf][am[i]][ak[i]]),
                       A + (long)(gm0 + am[i]) * K + k0 + ak[i]);
#pragma unroll
        for (int i = 0; i < 2; i++)
            cp_async16(smem_u32(&Bs[buf][am[i]][ak[i]]),
                       B + (long)(gn0 + am[i]) * K + k0 + ak[i]);
    };

    const int NI = K / BK;
    prefetch(0, 0); cp_commit();
    prefetch(1, 1); cp_commit();
    prefetch(2, 2); cp_commit();
    cp_wait<2>();
    __syncthreads();

    uint32_t aAddr0[4], bAddr0[2];
#pragma unroll
    for (int i = 0; i < 4; i++)
        aAddr0[i] = smem_u32(&As[0][wm0 + i*16 + (lane & 15)][(lane >> 4) * 8]);
#pragma unroll
    for (int jp = 0; jp < 2; jp++)
        bAddr0[jp] = smem_u32(&Bs[0][wn0 + jp*16 + (lane & 7) + ((lane >> 4) << 3)]
                                 [((lane >> 3) & 1) * 8]);

    float acc[4][4][4];
#pragma unroll
    for (int i = 0; i < 4; i++)
#pragma unroll
        for (int j = 0; j < 4; j++)
#pragma unroll
            for (int q = 0; q < 4; q++) acc[i][j][q] = 0.0f;

#pragma unroll 1
    for (int it = 0; it < NI; ++it) {
        const int buf = it % 3;
        const uint32_t aB = buf * A_BUF, bB = buf * B_BUF;
#pragma unroll
        for (int ks = 0; ks < BK; ks += 16) {
            uint32_t af[4][4], bq[2][4];
#pragma unroll
            for (int i = 0; i < 4; i++) ldsm_x4(af[i], aAddr0[i] + aB + ks * 2);
#pragma unroll
            for (int jp = 0; jp < 2; jp++) ldsm_x4(bq[jp], bAddr0[jp] + bB + ks * 2);
#pragma unroll
            for (int i = 0; i < 4; i++)
#pragma unroll
                for (int j = 0; j < 4; j++)
                    mma_f16(acc[i][j], af[i][0], af[i][1], af[i][2], af[i][3],
                            bq[j >> 1][(j & 1) * 2], bq[j >> 1][(j & 1) * 2 + 1]);
        }
        __syncthreads();
        if (it + 3 < NI) { prefetch(it + 3, buf); cp_commit(); }
        if (it + 1 < NI) {
            if (it + 3 < NI)       cp_wait<2>();
            else if (it + 2 < NI)  cp_wait<1>();
            else                   cp_wait<0>();
            __syncthreads();
        }
    }

    float*  Cf  = (float*)Cv;
    __half* Chp = (__half*)Cv;
#pragma unroll
    for (int i = 0; i < 4; i++) {
#pragma unroll
        for (int j = 0; j < 4; j++) {
#pragma unroll
            for (int h2 = 0; h2 < 2; h2++) {
                int m = gm0 + wm0 + i*16 + gid + h2*8;
                int n = gn0 + wn0 + j*8 + tg*2;
                float v0 = acc[i][j][h2*2 + 0];
                float v1 = acc[i][j][h2*2 + 1];
                if (bias) { v0 += bias[n]; v1 += bias[n+1]; }
                v0 *= scale; v1 *= scale;
                if (EPI == 0) {
                    *(float2*)(Cf + (long)m*ldc + n) = make_float2(v0, v1);
                } else if (EPI == 1) {          // [h][m][d]
                    int h = n >> 6, d = n & 63;
                    *(__half2*)(Chp + (long)h*M*HD + (long)m*HD + d) =
                        __floats2half2_rn(v0, v1);
                } else {                        // [h][d][m]
                    int h = n >> 6, d = n & 63;
                    __half* p = Chp + (long)h*HD*M + (long)d*M + m;
                    p[0] = __float2half_rn(v0);
                    p[M] = __float2half_rn(v1);
                }
            }
        }
    }
}

// ---------------------------------------------------------------------------
__global__ __launch_bounds__(256) void invred_k(const float* __restrict__ part,
                                                float* __restrict__ inv)
{
    const long row = (long)blockIdx.x * 256 + threadIdx.x;
    const float4 p = ((const float4*)part)[row];
    inv[row] = 1.0f / ((p.x + p.y) + (p.z + p.w));
}

// ---------------------------------------------------------------------------
__global__ __launch_bounds__(1024) void avg_k(const __half* __restrict__ P,
                                              const float* __restrict__ inv,
                                              float* __restrict__ out)
{
    const int t = blockIdx.x, tid = threadIdx.x;
    const long TS = (long)T_LEN * T_LEN;
    const __half* base = P + (long)t * T_LEN + tid * 4;
    float4 acc = make_float4(0.f, 0.f, 0.f, 0.f);
#pragma unroll
    for (int h = 0; h < H_NUM; h++) {
        const float iv = inv[h * T_LEN + t] * (1.0f / H_NUM);
        uint2 u = *(const uint2*)(base + (long)h * TS);
        float2 lo = __half22float2(*(__half2*)&u.x);
        float2 hi = __half22float2(*(__half2*)&u.y);
        acc.x += lo.x * iv; acc.y += lo.y * iv;
        acc.z += hi.x * iv; acc.w += hi.y * iv;
    }
    ((float4*)(out + (long)t * T_LEN))[tid] = acc;
}

// ---------------------------------------------------------------------------
extern "C" void kernel_launch(void* const* d_in, const int* in_sizes, int n_in,
                              void* d_out, int out_size)
{
    const float* q_in = (const float*)d_in[0];
    const float* k_in = (const float*)d_in[1];
    const float* v_in = (const float*)d_in[2];
    const float* w    = (const float*)d_in[3];
    const float* b    = (const float*)d_in[4];
    const float* ow   = (const float*)d_in[5];
    const float* ob   = (const float*)d_in[6];
    float* out = (float*)d_out;

    __half *Q, *K, *Vt, *P, *CTX, *X16, *W16;
    float *RSP, *INV;
    cudaGetSymbolAddress((void**)&Q,   g_Q);
    cudaGetSymbolAddress((void**)&K,   g_K);
    cudaGetSymbolAddress((void**)&Vt,  g_Vt);
    cudaGetSymbolAddress((void**)&P,   g_P);
    cudaGetSymbolAddress((void**)&CTX, g_CTX);
    cudaGetSymbolAddress((void**)&X16, g_X16);
    cudaGetSymbolAddress((void**)&W16, g_W16);
    cudaGetSymbolAddress((void**)&RSP, g_RSP);
    cudaGetSymbolAddress((void**)&INV, g_INV);

    const int T = T_LEN, E = E_DIM, H = H_NUM;
    const long EE = (long)E * E;
    const long TE = (long)T * E;
    dim3 blk(256);

    // fp32 -> fp16 conversions (numerically identical to old STS-time rounding)
    cvt_k<<<(int)(TE/4/256), 256>>>(q_in, X16);
    cvt_k<<<(int)(TE/4/256), 256>>>(k_in, X16 + TE);
    cvt_k<<<(int)(TE/4/256), 256>>>(v_in, X16 + 2*TE);
    cvt_k<<<(int)(3*EE/4/256), 256>>>(w,  W16);
    cvt_k<<<(int)(EE/4/256),   256>>>(ow, W16 + 3*EE);

    // QKV projections (all-fp16, cp.async pipeline)
    gemm16_k<1><<<dim3(E/128, T/128), blk>>>(
        X16,        W16,        b,       Q,   T, E, E, 0, 0.125f);
    gemm16_k<1><<<dim3(E/128, T/128), blk>>>(
        X16 + TE,   W16 + EE,   b + E,   K,   T, E, E, 0, 1.0f);
    gemm16_k<2><<<dim3(E/128, T/128), blk>>>(
        X16 + 2*TE, W16 + 2*EE, b + 2*E, Vt,  T, E, E, 0, 1.0f);

    // scores -> fp16 P + partial row sums
    scores_k<<<dim3(NBX_SCORES, T/128, H), blk>>>(Q, K, P, RSP);

    // row-sum reduce -> inv
    invred_k<<<(H*T)/256, 256>>>(RSP, INV);

    // head-average -> second half of d_out
    avg_k<<<T, 1024>>>(P, INV, out + (long)T * E);

    // ctx (dedicated pipelined kernel)
    ctx_k<<<dim3(T/128, H), blk>>>(P, Vt, INV, CTX);

    // out projection: fp16 CTX @ fp16 OW^T + bias -> fp32 out
    gemm16_k<0><<<dim3(E/128, T/128), blk>>>(
        CTX, W16 + 3*EE, ob, out, T, E, E, E, 1.0f);
}

// round 14
// speedup vs baseline: 1.0001x; 1.0001x over previous
#include <cuda_runtime.h>
#include <cuda_fp16.h>
#include <cstdint>

#define T_LEN 4096
#define E_DIM 1024
#define H_NUM 16
#define HD    64
#define NBX_SCORES 4     // column splits in scores kernel
#define NT_SC 8          // K-tiles per scores block

// Scratch (allocation-free rule: __device__ globals)
__device__ __half g_Q  [(long)H_NUM * T_LEN * HD];
__device__ __half g_K  [(long)H_NUM * T_LEN * HD];
__device__ __half g_Vt [(long)H_NUM * HD * T_LEN];
__device__ __half g_P  [(long)H_NUM * T_LEN * T_LEN];
__device__ __half g_CTX[(long)T_LEN * E_DIM];
__device__ __half g_X16[(long)3 * T_LEN * E_DIM];        // fp16 q_in|k_in|v_in
__device__ __half g_W16[(long)4 * E_DIM * E_DIM];        // fp16 wq|wk|wv|ow
__device__ float  g_RSP[(long)H_NUM * T_LEN * NBX_SCORES];
__device__ float  g_INV[(long)H_NUM * T_LEN];

__device__ __forceinline__ float ex2(float x) {
    float r;
    asm("ex2.approx.f32 %0, %1;" : "=f"(r) : "f"(x));
    return r;
}
__device__ __forceinline__ uint32_t smem_u32(const void* p) {
    return (uint32_t)__cvta_generic_to_shared(p);
}
__device__ __forceinline__ void ldsm_x4(uint32_t r[4], uint32_t addr) {
    asm volatile("ldmatrix.sync.aligned.m8n8.x4.shared.b16 {%0,%1,%2,%3}, [%4];"
        : "=r"(r[0]), "=r"(r[1]), "=r"(r[2]), "=r"(r[3]) : "r"(addr));
}
__device__ __forceinline__ void cp_async16(uint32_t saddr, const void* gaddr) {
    asm volatile("cp.async.cg.shared.global [%0], [%1], 16;" :: "r"(saddr), "l"(gaddr));
}
__device__ __forceinline__ void cp_commit() { asm volatile("cp.async.commit_group;"); }
template<int N>
__device__ __forceinline__ void cp_wait() {
    asm volatile("cp.async.wait_group %0;" :: "n"(N));
}

__device__ __forceinline__ void mma_f16(float c[4],
    uint32_t a0, uint32_t a1, uint32_t a2, uint32_t a3,
    uint32_t b0, uint32_t b1)
{
    asm volatile(
        "mma.sync.aligned.m16n8k16.row.col.f32.f16.f16.f32 "
        "{%0,%1,%2,%3}, {%4,%5,%6,%7}, {%8,%9}, {%0,%1,%2,%3};"
        : "+f"(c[0]), "+f"(c[1]), "+f"(c[2]), "+f"(c[3])
        : "r"(a0), "r"(a1), "r"(a2), "r"(a3), "r"(b0), "r"(b1));
}

#define LOG2E 1.4426950408889634f
#define PSHIFT 2.0f

// ---------------------------------------------------------------------------
// fp32 -> fp16 bulk convert
// ---------------------------------------------------------------------------
__global__ __launch_bounds__(256) void cvt_k(const float* __restrict__ src,
                                             __half* __restrict__ dst)
{
    const long i = ((long)blockIdx.x * 256 + threadIdx.x) * 4;
    float4 t = *(const float4*)(src + i);
    *(__half2*)(dst + i)     = __floats2half2_rn(t.x, t.y);
    *(__half2*)(dst + i + 2) = __floats2half2_rn(t.z, t.w);
}

// ===========================================================================
// Scores (R12 version, unchanged): 2-stage cp.async, Q frags in regs,
// STG.128 epilogue via quad transpose.
// ===========================================================================
__global__ __launch_bounds__(256, 2)
void scores_k(const __half* __restrict__ Q, const __half* __restrict__ Kp,
              __half* __restrict__ P, float* __restrict__ rsp)
{
    __shared__ __half Qs[128][72];
    __shared__ __half Ks[2][128][72];
    __shared__ float  srs[512];

    const int tid  = threadIdx.x;
    const int warp = tid >> 5, lane = tid & 31;
    const int gid = lane >> 2, tg = lane & 3;
    const int wm0 = (warp >> 2) * 64;
    const int wn0 = (warp & 3) * 32;
    const int gm0 = blockIdx.y * 128;
    const int cbase = blockIdx.x * (NT_SC * 128);

    const __half* Ah = Q  + (long)blockIdx.z * T_LEN * HD + (long)gm0 * HD;
    const __half* Kh = Kp + (long)blockIdx.z * T_LEN * HD + (long)cbase * HD;

    int lm[4], lk[4];
#pragma unroll
    for (int i = 0; i < 4; i++) {
        const int idx = (tid + i * 256) * 8;
        lm[i] = idx >> 6; lk[i] = idx & 63;
    }
    auto prefetchK = [&](int nt, int buf) {
#pragma unroll
        for (int i = 0; i < 4; i++)
            cp_async16(smem_u32(&Ks[buf][lm[i]][lk[i]]),
                       Kh + ((long)nt * 128 + lm[i]) * HD + lk[i]);
    };

#pragma unroll
    for (int i = 0; i < 4; i++)
        cp_async16(smem_u32(&Qs[lm[i]][lk[i]]), Ah + (long)lm[i] * HD + lk[i]);
    prefetchK(0, 0); cp_commit();
    prefetchK(1, 1); cp_commit();
    cp_wait<1>();
    __syncthreads();

    uint32_t af[4][4][4];
#pragma unroll
    for (int i = 0; i < 4; i++) {
        const uint32_t a = smem_u32(&Qs[wm0 + i*16 + (lane & 15)][(lane >> 4) * 8]);
#pragma unroll
        for (int ks = 0; ks < 4; ks++) ldsm_x4(af[ks][i], a + ks * 32);
    }

    uint32_t bAddr[2][2];
#pragma unroll
    for (int buf = 0; buf < 2; buf++)
#pragma unroll
        for (int jp = 0; jp < 2; jp++)
            bAddr[buf][jp] = smem_u32(
                &Ks[buf][wn0 + jp*16 + (lane & 7) + ((lane >> 4) << 3)]
                        [((lane >> 3) & 1) * 8]);

    float rsum[4][2];
#pragma unroll
    for (int i = 0; i < 4; i++) { rsum[i][0] = 0.f; rsum[i][1] = 0.f; }

    __half* Ch = P + (long)blockIdx.z * T_LEN * T_LEN;

#pragma unroll 1
    for (int nt = 0; nt < NT_SC; nt++) {
        const int buf = nt & 1;

        float acc[4][4][4];
#pragma unroll
        for (int i = 0; i < 4; i++)
#pragma unroll
            for (int j = 0; j < 4; j++)
#pragma unroll
                for (int q = 0; q < 4; q++) acc[i][j][q] = 0.0f;

#pragma unroll
        for (int ks = 0; ks < 4; ks++) {
            uint32_t bq[2][4];
#pragma unroll
            for (int jp = 0; jp < 2; jp++)
                ldsm_x4(bq[jp], bAddr[buf][jp] + ks * 32);
#pragma unroll
            for (int i = 0; i < 4; i++)
#pragma unroll
                for (int j = 0; j < 4; j++)
                    mma_f16(acc[i][j], af[ks][i][0], af[ks][i][1],
                            af[ks][i][2], af[ks][i][3],
                            bq[j >> 1][(j & 1) * 2], bq[j >> 1][(j & 1) * 2 + 1]);
        }

        const int n0t = cbase + nt * 128;
#pragma unroll
        for (int i = 0; i < 4; i++) {
#pragma unroll
            for (int h2 = 0; h2 < 2; h2++) {
                uint32_t hp[4];
#pragma unroll
                for (int j = 0; j < 4; j++) {
                    float v0 = ex2(fmaf(acc[i][j][h2*2 + 0], LOG2E, PSHIFT));
                    float v1 = ex2(fmaf(acc[i][j][h2*2 + 1], LOG2E, PSHIFT));
                    rsum[i][h2] += v0 + v1;
                    __half2 h = __floats2half2_rn(v0, v1);
                    hp[j] = *(uint32_t*)&h;
                }
                {
                    uint32_t t, r;
                    t = (tg & 1) ? hp[0] : hp[1];
                    r = __shfl_xor_sync(0xffffffffu, t, 1);
                    if (tg & 1) hp[0] = r; else hp[1] = r;
                    t = (tg & 1) ? hp[2] : hp[3];
                    r = __shfl_xor_sync(0xffffffffu, t, 1);
                    if (tg & 1) hp[2] = r; else hp[3] = r;
                    t = (tg & 2) ? hp[0] : hp[2];
                    r = __shfl_xor_sync(0xffffffffu, t, 2);
                    if (tg & 2) hp[0] = r; else hp[2] = r;
                    t = (tg & 2) ? hp[1] : hp[3];
                    r = __shfl_xor_sync(0xffffffffu, t, 2);
                    if (tg & 2) hp[1] = r; else hp[3] = r;
                }
                const int m = gm0 + wm0 + i * 16 + gid + h2 * 8;
                const int n = n0t + wn0 + tg * 8;
                *(uint4*)(Ch + (long)m * T_LEN + n) =
                    make_uint4(hp[0], hp[1], hp[2], hp[3]);
            }
        }

        __syncthreads();
        if (nt + 2 < NT_SC) { prefetchK(nt + 2, buf); cp_commit(); }
        if (nt + 1 < NT_SC) {
            if (nt + 2 < NT_SC) cp_wait<1>(); else cp_wait<0>();
            __syncthreads();
        }
    }

#pragma unroll
    for (int i = 0; i < 4; i++)
#pragma unroll
        for (int h2 = 0; h2 < 2; h2++)
#pragma unroll
            for (int o = 1; o < 4; o <<= 1)
                rsum[i][h2] += __shfl_xor_sync(0xffffffffu, rsum[i][h2], o);
    if (tg == 0) {
        const int wn = warp & 3;
#pragma unroll
        for (int i = 0; i < 4; i++)
#pragma unroll
            for (int h2 = 0; h2 < 2; h2++)
                srs[wn * 128 + wm0 + i * 16 + h2 * 8 + gid] = rsum[i][h2];
    }
    __syncthreads();
    if (tid < 128) {
        float s = srs[tid] + srs[128 + tid] + srs[256 + tid] + srs[384 + tid];
        rsp[((long)blockIdx.z * T_LEN + gm0 + tid) * NBX_SCORES + blockIdx.x] = s;
    }
}

// ===========================================================================
// Dedicated ctx kernel (R11, unchanged).
// ===========================================================================
#define CTX_BK 64
#define CTX_NI (T_LEN / CTX_BK)   // 64

__global__ __launch_bounds__(256, 2)
void ctx_k(const __half* __restrict__ P, const __half* __restrict__ Vt,
           const float* __restrict__ inv, __half* __restrict__ CTX)
{
    __shared__ __half Ps[3][128][72];
    __shared__ __half Vs[3][64][72];

    const int tid  = threadIdx.x;
    const int warp = tid >> 5, lane = tid & 31;
    const int gid = lane >> 2, tg = lane & 3;
    const int wm0 = (warp >> 1) * 32;
    const int wn0 = (warp & 1) * 32;
    const int gm0 = blockIdx.x * 128;
    const int h   = blockIdx.y;

    const __half* Ph = P  + (long)h * T_LEN * T_LEN + (long)gm0 * T_LEN;
    const __half* Vh = Vt + (long)h * HD * T_LEN;

    int am[4], ak[4], bd[2], bk[2];
#pragma unroll
    for (int i = 0; i < 4; i++) {
        const int idx = (tid + i * 256) * 8;
        am[i] = idx >> 6; ak[i] = idx & 63;
    }
#pragma unroll
    for (int i = 0; i < 2; i++) {
        const int idx = (tid + i * 256) * 8;
        bd[i] = idx >> 6; bk[i] = idx & 63;
    }

    auto prefetch = [&](int it, int buf) {
        const int s0 = it * CTX_BK;
#pragma unroll
        for (int i = 0; i < 4; i++)
            cp_async16(smem_u32(&Ps[buf][am[i]][ak[i]]),
                       Ph + (long)am[i] * T_LEN + s0 + ak[i]);
#pragma unroll
        for (int i = 0; i < 2; i++)
            cp_async16(smem_u32(&Vs[buf][bd[i]][bk[i]]),
                       Vh + (long)bd[i] * T_LEN + s0 + bk[i]);
    };

    prefetch(0, 0); cp_commit();
    prefetch(1, 1); cp_commit();
    prefetch(2, 2); cp_commit();
    cp_wait<2>();
    __syncthreads();

    uint32_t aAddr[3][2], bAddr[3][2];
#pragma unroll
    for (int st = 0; st < 3; st++) {
#pragma unroll
        for (int i = 0; i < 2; i++)
            aAddr[st][i] = smem_u32(
                &Ps[st][wm0 + i*16 + (lane & 15)][(lane >> 4) * 8]);
#pragma unroll
        for (int jp = 0; jp < 2; jp++)
            bAddr[st][jp] = smem_u32(
                &Vs[st][wn0 + jp*16 + (lane & 7) + ((lane >> 4) << 3)]
                       [((lane >> 3) & 1) * 8]);
    }

    float acc[2][4][4];
#pragma unroll
    for (int i = 0; i < 2; i++)
#pragma unroll
        for (int j = 0; j < 4; j++)
#pragma unroll
            for (int q = 0; q < 4; q++) acc[i][j][q] = 0.0f;

#pragma unroll 1
    for (int it = 0; it < CTX_NI; ++it) {
        const int buf = it % 3;
#pragma unroll
        for (int ks = 0; ks < 4; ks++) {
            uint32_t af[2][4], bq[2][4];
#pragma unroll
            for (int i = 0; i < 2; i++) ldsm_x4(af[i], aAddr[buf][i] + ks * 32);
#pragma unroll
            for (int jp = 0; jp < 2; jp++) ldsm_x4(bq[jp], bAddr[buf][jp] + ks * 32);
#pragma unroll
            for (int i = 0; i < 2; i++)
#pragma unroll
                for (int j = 0; j < 4; j++)
                    mma_f16(acc[i][j], af[i][0], af[i][1], af[i][2], af[i][3],
                            bq[j >> 1][(j & 1) * 2], bq[j >> 1][(j & 1) * 2 + 1]);
        }
        __syncthreads();
        if (it + 3 < CTX_NI) { prefetch(it + 3, buf); cp_commit(); }
        if (it + 1 < CTX_NI) {
            if (it + 3 < CTX_NI)       cp_wait<2>();
            else if (it + 2 < CTX_NI)  cp_wait<1>();
            else                       cp_wait<0>();
            __syncthreads();
        }
    }

    const float* invh = inv + (long)h * T_LEN;
#pragma unroll
    for (int i = 0; i < 2; i++) {
#pragma unroll
        for (int j = 0; j < 4; j++) {
#pragma unroll
            for (int h2 = 0; h2 < 2; h2++) {
                const int m = gm0 + wm0 + i*16 + gid + h2*8;
                const int n = h * HD + wn0 + j*8 + tg*2;
                const float sc = invh[m];
                float v0 = acc[i][j][h2*2 + 0] * sc;
                float v1 = acc[i][j][h2*2 + 1] * sc;
                *(__half2*)(CTX + (long)m * E_DIM + n) = __floats2half2_rn(v0, v1);
            }
        }
    }
}

// ===========================================================================
// All-fp16 GEMM, 3-stage cp.async pipeline, BM=BN=128, BK=32, 256 thr (2x4).
//   C = (A @ B^T + bias) * scale
//   EPI 0: fp32 C[m*ldc+n]; 1: fp16 head-scatter [h][m][d]; 2: fp16 [h][d][m]
// ===========================================================================
template<int EPI>
__global__ __launch_bounds__(256, 2)
void gemm16_k(const __half* __restrict__ A, const __half* __restrict__ B,
              const float* __restrict__ bias, void* __restrict__ Cv,
              int M, int N, int K, int ldc, float scale)
{
    constexpr int BK = 32;
    __shared__ __half As[3][128][40];
    __shared__ __half Bs[3][128][40];
    constexpr uint32_t A_BUF = 128 * 40 * 2;
    constexpr uint32_t B_BUF = 128 * 40 * 2;

    const int tid  = threadIdx.x;
    const int warp = tid >> 5, lane = tid & 31;
    const int wm0 = (warp >> 2) * 64;   // WARPS_M=2 -> WM=64, MT=4
    const int wn0 = (warp & 3) * 32;    // WARPS_N=4 -> WN=32, NT=4
    const int gid = lane >> 2, tg = lane & 3;
    const int gm0 = blockIdx.y * 128, gn0 = blockIdx.x * 128;

    // 128x32 halfs per tile = 512 16B-chunks -> 2 per thread
    int am[2], ak[2];
#pragma unroll
    for (int i = 0; i < 2; i++) {
        const int idx = (tid + i * 256) * 8;
        am[i] = idx >> 5; ak[i] = idx & 31;
    }

    auto prefetch = [&](int it, int buf) {
        const int k0 = it * BK;
#pragma unroll
        for (int i = 0; i < 2; i++)
            cp_async16(smem_u32(&As[buf][am[i]][ak[i]]),
                       A + (long)(gm0 + am[i]) * K + k0 + ak[i]);
#pragma unroll
        for (int i = 0; i < 2; i++)
            cp_async16(smem_u32(&Bs[buf][am[i]][ak[i]]),
                       B + (long)(gn0 + am[i]) * K + k0 + ak[i]);
    };

    const int NI = K / BK;
    prefetch(0, 0); cp_commit();
    prefetch(1, 1); cp_commit();
    prefetch(2, 2); cp_commit();
    cp_wait<2>();
    __syncthreads();

    uint32_t aAddr0[4], bAddr0[2];
#pragma unroll
    for (int i = 0; i < 4; i++)
        aAddr0[i] = smem_u32(&As[0][wm0 + i*16 + (lane & 15)][(lane >> 4) * 8]);
#pragma unroll
    for (int jp = 0; jp < 2; jp++)
        bAddr0[jp] = smem_u32(&Bs[0][wn0 + jp*16 + (lane & 7) + ((lane >> 4) << 3)]
                                 [((lane >> 3) & 1) * 8]);

    float acc[4][4][4];
#pragma unroll
    for (int i = 0; i < 4; i++)
#pragma unroll
        for (int j = 0; j < 4; j++)
#pragma unroll
            for (int q = 0; q < 4; q++) acc[i][j][q] = 0.0f;

#pragma unroll 1
    for (int it = 0; it < NI; ++it) {
        const int buf = it % 3;
        const uint32_t aB = buf * A_BUF, bB = buf * B_BUF;
#pragma unroll
        for (int ks = 0; ks < BK; ks += 16) {
            uint32_t af[4][4], bq[2][4];
#pragma unroll
            for (int i = 0; i < 4; i++) ldsm_x4(af[i], aAddr0[i] + aB + ks * 2);
#pragma unroll
            for (int jp = 0; jp < 2; jp++) ldsm_x4(bq[jp], bAddr0[jp] + bB + ks * 2);
#pragma unroll
            for (int i = 0; i < 4; i++)
#pragma unroll
                for (int j = 0; j < 4; j++)
                    mma_f16(acc[i][j], af[i][0], af[i][1], af[i][2], af[i][3],
                            bq[j >> 1][(j & 1) * 2], bq[j >> 1][(j & 1) * 2 + 1]);
        }
        __syncthreads();
        if (it + 3 < NI) { prefetch(it + 3, buf); cp_commit(); }
        if (it + 1 < NI) {
            if (it + 3 < NI)       cp_wait<2>();
            else if (it + 2 < NI)  cp_wait<1>();
            else                   cp_wait<0>();
            __syncthreads();
        }
    }

    float*  Cf  = (float*)Cv;
    __half* Chp = (__half*)Cv;
#pragma unroll
    for (int i = 0; i < 4; i++) {
#pragma unroll
        for (int j = 0; j < 4; j++) {
#pragma unroll
            for (int h2 = 0; h2 < 2; h2++) {
                int m = gm0 + wm0 + i*16 + gid + h2*8;
                int n = gn0 + wn0 + j*8 + tg*2;
                float v0 = acc[i][j][h2*2 + 0];
                float v1 = acc[i][j][h2*2 + 1];
                if (bias) { v0 += bias[n]; v1 += bias[n+1]; }
                v0 *= scale; v1 *= scale;
                if (EPI == 0) {
                    *(float2*)(Cf + (long)m*ldc + n) = make_float2(v0, v1);
                } else if (EPI == 1) {          // [h][m][d]
                    int h = n >> 6, d = n & 63;
                    *(__half2*)(Chp + (long)h*M*HD + (long)m*HD + d) =
                        __floats2half2_rn(v0, v1);
                } else {                        // [h][d][m]
                    int h = n >> 6, d = n & 63;
                    __half* p = Chp + (long)h*HD*M + (long)d*M + m;
                    p[0] = __float2half_rn(v0);
                    p[M] = __float2half_rn(v1);
                }
            }
        }
    }
}

// ---------------------------------------------------------------------------
__global__ __launch_bounds__(256) void invred_k(const float* __restrict__ part,
                                                float* __restrict__ inv)
{
    const long row = (long)blockIdx.x * 256 + threadIdx.x;
    const float4 p = ((const float4*)part)[row];
    inv[row] = 1.0f / ((p.x + p.y) + (p.z + p.w));
}

// ---------------------------------------------------------------------------
__global__ __launch_bounds__(1024) void avg_k(const __half* __restrict__ P,
                                              const float* __restrict__ inv,
                                              float* __restrict__ out)
{
    const int t = blockIdx.x, tid = threadIdx.x;
    const long TS = (long)T_LEN * T_LEN;
    const __half* base = P + (long)t * T_LEN + tid * 4;
    float4 acc = make_float4(0.f, 0.f, 0.f, 0.f);
#pragma unroll
    for (int h = 0; h < H_NUM; h++) {
        const float iv = inv[h * T_LEN + t] * (1.0f / H_NUM);
        uint2 u = *(const uint2*)(base + (long)h * TS);
        float2 lo = __half22float2(*(__half2*)&u.x);
        float2 hi = __half22float2(*(__half2*)&u.y);
        acc.x += lo.x * iv; acc.y += lo.y * iv;
        acc.z += hi.x * iv; acc.w += hi.y * iv;
    }
    ((float4*)(out + (long)t * T_LEN))[tid] = acc;
}

// ---------------------------------------------------------------------------
extern "C" void kernel_launch(void* const* d_in, const int* in_sizes, int n_in,
                              void* d_out, int out_size)
{
    const float* q_in = (const float*)d_in[0];
    const float* k_in = (const float*)d_in[1];
    const float* v_in = (const float*)d_in[2];
    const float* w    = (const float*)d_in[3];
    const float* b    = (const float*)d_in[4];
    const float* ow   = (const float*)d_in[5];
    const float* ob   = (const float*)d_in[6];
    float* out = (float*)d_out;

    __half *Q, *K, *Vt, *P, *CTX, *X16, *W16;
    float *RSP, *INV;
    cudaGetSymbolAddress((void**)&Q,   g_Q);
    cudaGetSymbolAddress((void**)&K,   g_K);
    cudaGetSymbolAddress((void**)&Vt,  g_Vt);
    cudaGetSymbolAddress((void**)&P,   g_P);
    cudaGetSymbolAddress((void**)&CTX, g_CTX);
    cudaGetSymbolAddress((void**)&X16, g_X16);
    cudaGetSymbolAddress((void**)&W16, g_W16);
    cudaGetSymbolAddress((void**)&RSP, g_RSP);
    cudaGetSymbolAddress((void**)&INV, g_INV);

    const int T = T_LEN, E = E_DIM, H = H_NUM;
    const long EE = (long)E * E;
    const long TE = (long)T * E;
    dim3 blk(256);

    // fp32 -> fp16 conversions (numerically identical to old STS-time rounding)
    cvt_k<<<(int)(TE/4/256), 256>>>(q_in, X16);
    cvt_k<<<(int)(TE/4/256), 256>>>(k_in, X16 + TE);
    cvt_k<<<(int)(TE/4/256), 256>>>(v_in, X16 + 2*TE);
    cvt_k<<<(int)(3*EE/4/256), 256>>>(w,  W16);
    cvt_k<<<(int)(EE/4/256),   256>>>(ow, W16 + 3*EE);

    // QKV projections (all-fp16, cp.async pipeline)
    gemm16_k<1><<<dim3(E/128, T/128), blk>>>(
        X16,        W16,        b,       Q,   T, E, E, 0, 0.125f);
    gemm16_k<1><<<dim3(E/128, T/128), blk>>>(
        X16 + TE,   W16 + EE,   b + E,   K,   T, E, E, 0, 1.0f);
    gemm16_k<2><<<dim3(E/128, T/128), blk>>>(
        X16 + 2*TE, W16 + 2*EE, b + 2*E, Vt,  T, E, E, 0, 1.0f);

    // scores -> fp16 P + partial row sums
    scores_k<<<dim3(NBX_SCORES, T/128, H), blk>>>(Q, K, P, RSP);

    // row-sum reduce -> inv
    invred_k<<<(H*T)/256, 256>>>(RSP, INV);

    // head-average -> second half of d_out
    avg_k<<<T, 1024>>>(P, INV, out + (long)T * E);

    // ctx (dedicated pipelined kernel)
    ctx_k<<<dim3(T/128, H), blk>>>(P, Vt, INV, CTX);

    // out projection: fp16 CTX @ fp16 OW^T + bias -> fp32 out
    gemm16_k<0><<<dim3(E/128, T/128), blk>>>(
        CTX, W16 + 3*EE, ob, out, T, E, E, E, 1.0f);
}

// round 15
// speedup vs baseline: 1.0028x; 1.0027x over previous
#include <cuda_runtime.h>
#include <cuda_fp16.h>
#include <cstdint>

#define T_LEN 4096
#define E_DIM 1024
#define H_NUM 16
#define HD    64
#define NBX_SCORES 4     // column splits in scores kernel
#define NT_SC 8          // K-tiles per scores block

// Scratch (allocation-free rule: __device__ globals)
__device__ __half g_Q  [(long)H_NUM * T_LEN * HD];
__device__ __half g_K  [(long)H_NUM * T_LEN * HD];
__device__ __half g_Vt [(long)H_NUM * HD * T_LEN];
__device__ __half g_P  [(long)H_NUM * T_LEN * T_LEN];
__device__ __half g_CTX[(long)T_LEN * E_DIM];
__device__ __half g_X16[(long)3 * T_LEN * E_DIM];        // fp16 q_in|k_in|v_in
__device__ __half g_W16[(long)4 * E_DIM * E_DIM];        // fp16 wq|wk|wv|ow
__device__ float  g_RSP[(long)H_NUM * T_LEN * NBX_SCORES];
__device__ float  g_INV[(long)H_NUM * T_LEN];

__device__ __forceinline__ float ex2(float x) {
    float r;
    asm("ex2.approx.f32 %0, %1;" : "=f"(r) : "f"(x));
    return r;
}
__device__ __forceinline__ uint32_t smem_u32(const void* p) {
    return (uint32_t)__cvta_generic_to_shared(p);
}
__device__ __forceinline__ void ldsm_x4(uint32_t r[4], uint32_t addr) {
    asm volatile("ldmatrix.sync.aligned.m8n8.x4.shared.b16 {%0,%1,%2,%3}, [%4];"
        : "=r"(r[0]), "=r"(r[1]), "=r"(r[2]), "=r"(r[3]) : "r"(addr));
}
__device__ __forceinline__ void cp_async16(uint32_t saddr, const void* gaddr) {
    asm volatile("cp.async.cg.shared.global [%0], [%1], 16;" :: "r"(saddr), "l"(gaddr));
}
__device__ __forceinline__ void cp_commit() { asm volatile("cp.async.commit_group;"); }
template<int N>
__device__ __forceinline__ void cp_wait() {
    asm volatile("cp.async.wait_group %0;" :: "n"(N));
}

__device__ __forceinline__ void mma_f16(float c[4],
    uint32_t a0, uint32_t a1, uint32_t a2, uint32_t a3,
    uint32_t b0, uint32_t b1)
{
    asm volatile(
        "mma.sync.aligned.m16n8k16.row.col.f32.f16.f16.f32 "
        "{%0,%1,%2,%3}, {%4,%5,%6,%7}, {%8,%9}, {%0,%1,%2,%3};"
        : "+f"(c[0]), "+f"(c[1]), "+f"(c[2]), "+f"(c[3])
        : "r"(a0), "r"(a1), "r"(a2), "r"(a3), "r"(b0), "r"(b1));
}

#define LOG2E 1.4426950408889634f
#define PSHIFT 2.0f

// ---------------------------------------------------------------------------
// fp32 -> fp16 bulk convert
// ---------------------------------------------------------------------------
__global__ __launch_bounds__(256) void cvt_k(const float* __restrict__ src,
                                             __half* __restrict__ dst)
{
    const long i = ((long)blockIdx.x * 256 + threadIdx.x) * 4;
    float4 t = *(const float4*)(src + i);
    *(__half2*)(dst + i)     = __floats2half2_rn(t.x, t.y);
    *(__half2*)(dst + i + 2) = __floats2half2_rn(t.z, t.w);
}

// ===========================================================================
// Scores (R12 version, unchanged): 2-stage cp.async, Q frags in regs,
// STG.128 epilogue via quad transpose.
// ===========================================================================
__global__ __launch_bounds__(256, 2)
void scores_k(const __half* __restrict__ Q, const __half* __restrict__ Kp,
              __half* __restrict__ P, float* __restrict__ rsp)
{
    __shared__ __half Qs[128][72];
    __shared__ __half Ks[2][128][72];
    __shared__ float  srs[512];

    const int tid  = threadIdx.x;
    const int warp = tid >> 5, lane = tid & 31;
    const int gid = lane >> 2, tg = lane & 3;
    const int wm0 = (warp >> 2) * 64;
    const int wn0 = (warp & 3) * 32;
    const int gm0 = blockIdx.y * 128;
    const int cbase = blockIdx.x * (NT_SC * 128);

    const __half* Ah = Q  + (long)blockIdx.z * T_LEN * HD + (long)gm0 * HD;
    const __half* Kh = Kp + (long)blockIdx.z * T_LEN * HD + (long)cbase * HD;

    int lm[4], lk[4];
#pragma unroll
    for (int i = 0; i < 4; i++) {
        const int idx = (tid + i * 256) * 8;
        lm[i] = idx >> 6; lk[i] = idx & 63;
    }
    auto prefetchK = [&](int nt, int buf) {
#pragma unroll
        for (int i = 0; i < 4; i++)
            cp_async16(smem_u32(&Ks[buf][lm[i]][lk[i]]),
                       Kh + ((long)nt * 128 + lm[i]) * HD + lk[i]);
    };

#pragma unroll
    for (int i = 0; i < 4; i++)
        cp_async16(smem_u32(&Qs[lm[i]][lk[i]]), Ah + (long)lm[i] * HD + lk[i]);
    prefetchK(0, 0); cp_commit();
    prefetchK(1, 1); cp_commit();
    cp_wait<1>();
    __syncthreads();

    uint32_t af[4][4][4];
#pragma unroll
    for (int i = 0; i < 4; i++) {
        const uint32_t a = smem_u32(&Qs[wm0 + i*16 + (lane & 15)][(lane >> 4) * 8]);
#pragma unroll
        for (int ks = 0; ks < 4; ks++) ldsm_x4(af[ks][i], a + ks * 32);
    }

    uint32_t bAddr[2][2];
#pragma unroll
    for (int buf = 0; buf < 2; buf++)
#pragma unroll
        for (int jp = 0; jp < 2; jp++)
            bAddr[buf][jp] = smem_u32(
                &Ks[buf][wn0 + jp*16 + (lane & 7) + ((lane >> 4) << 3)]
                        [((lane >> 3) & 1) * 8]);

    float rsum[4][2];
#pragma unroll
    for (int i = 0; i < 4; i++) { rsum[i][0] = 0.f; rsum[i][1] = 0.f; }

    __half* Ch = P + (long)blockIdx.z * T_LEN * T_LEN;

#pragma unroll 1
    for (int nt = 0; nt < NT_SC; nt++) {
        const int buf = nt & 1;

        float acc[4][4][4];
#pragma unroll
        for (int i = 0; i < 4; i++)
#pragma unroll
            for (int j = 0; j < 4; j++)
#pragma unroll
                for (int q = 0; q < 4; q++) acc[i][j][q] = 0.0f;

#pragma unroll
        for (int ks = 0; ks < 4; ks++) {
            uint32_t bq[2][4];
#pragma unroll
            for (int jp = 0; jp < 2; jp++)
                ldsm_x4(bq[jp], bAddr[buf][jp] + ks * 32);
#pragma unroll
            for (int i = 0; i < 4; i++)
#pragma unroll
                for (int j = 0; j < 4; j++)
                    mma_f16(acc[i][j], af[ks][i][0], af[ks][i][1],
                            af[ks][i][2], af[ks][i][3],
                            bq[j >> 1][(j & 1) * 2], bq[j >> 1][(j & 1) * 2 + 1]);
        }

        const int n0t = cbase + nt * 128;
#pragma unroll
        for (int i = 0; i < 4; i++) {
#pragma unroll
            for (int h2 = 0; h2 < 2; h2++) {
                uint32_t hp[4];
#pragma unroll
                for (int j = 0; j < 4; j++) {
                    float v0 = ex2(fmaf(acc[i][j][h2*2 + 0], LOG2E, PSHIFT));
                    float v1 = ex2(fmaf(acc[i][j][h2*2 + 1], LOG2E, PSHIFT));
                    rsum[i][h2] += v0 + v1;
                    __half2 h = __floats2half2_rn(v0, v1);
                    hp[j] = *(uint32_t*)&h;
                }
                {
                    uint32_t t, r;
                    t = (tg & 1) ? hp[0] : hp[1];
                    r = __shfl_xor_sync(0xffffffffu, t, 1);
                    if (tg & 1) hp[0] = r; else hp[1] = r;
                    t = (tg & 1) ? hp[2] : hp[3];
                    r = __shfl_xor_sync(0xffffffffu, t, 1);
                    if (tg & 1) hp[2] = r; else hp[3] = r;
                    t = (tg & 2) ? hp[0] : hp[2];
                    r = __shfl_xor_sync(0xffffffffu, t, 2);
                    if (tg & 2) hp[0] = r; else hp[2] = r;
                    t = (tg & 2) ? hp[1] : hp[3];
                    r = __shfl_xor_sync(0xffffffffu, t, 2);
                    if (tg & 2) hp[1] = r; else hp[3] = r;
                }
                const int m = gm0 + wm0 + i * 16 + gid + h2 * 8;
                const int n = n0t + wn0 + tg * 8;
                *(uint4*)(Ch + (long)m * T_LEN + n) =
                    make_uint4(hp[0], hp[1], hp[2], hp[3]);
            }
        }

        __syncthreads();
        if (nt + 2 < NT_SC) { prefetchK(nt + 2, buf); cp_commit(); }
        if (nt + 1 < NT_SC) {
            if (nt + 2 < NT_SC) cp_wait<1>(); else cp_wait<0>();
            __syncthreads();
        }
    }

#pragma unroll
    for (int i = 0; i < 4; i++)
#pragma unroll
        for (int h2 = 0; h2 < 2; h2++)
#pragma unroll
            for (int o = 1; o < 4; o <<= 1)
                rsum[i][h2] += __shfl_xor_sync(0xffffffffu, rsum[i][h2], o);
    if (tg == 0) {
        const int wn = warp & 3;
#pragma unroll
        for (int i = 0; i < 4; i++)
#pragma unroll
            for (int h2 = 0; h2 < 2; h2++)
                srs[wn * 128 + wm0 + i * 16 + h2 * 8 + gid] = rsum[i][h2];
    }
    __syncthreads();
    if (tid < 128) {
        float s = srs[tid] + srs[128 + tid] + srs[256 + tid] + srs[384 + tid];
        rsp[((long)blockIdx.z * T_LEN + gm0 + tid) * NBX_SCORES + blockIdx.x] = s;
    }
}

// ===========================================================================
// Dedicated ctx kernel (R11, unchanged).
// ===========================================================================
#define CTX_BK 64
#define CTX_NI (T_LEN / CTX_BK)   // 64

__global__ __launch_bounds__(256, 2)
void ctx_k(const __half* __restrict__ P, const __half* __restrict__ Vt,
           const float* __restrict__ inv, __half* __restrict__ CTX)
{
    __shared__ __half Ps[3][128][72];
    __shared__ __half Vs[3][64][72];

    const int tid  = threadIdx.x;
    const int warp = tid >> 5, lane = tid & 31;
    const int gid = lane >> 2, tg = lane & 3;
    const int wm0 = (warp >> 1) * 32;
    const int wn0 = (warp & 1) * 32;
    const int gm0 = blockIdx.x * 128;
    const int h   = blockIdx.y;

    const __half* Ph = P  + (long)h * T_LEN * T_LEN + (long)gm0 * T_LEN;
    const __half* Vh = Vt + (long)h * HD * T_LEN;

    int am[4], ak[4], bd[2], bk[2];
#pragma unroll
    for (int i = 0; i < 4; i++) {
        const int idx = (tid + i * 256) * 8;
        am[i] = idx >> 6; ak[i] = idx & 63;
    }
#pragma unroll
    for (int i = 0; i < 2; i++) {
        const int idx = (tid + i * 256) * 8;
        bd[i] = idx >> 6; bk[i] = idx & 63;
    }

    auto prefetch = [&](int it, int buf) {
        const int s0 = it * CTX_BK;
#pragma unroll
        for (int i = 0; i < 4; i++)
            cp_async16(smem_u32(&Ps[buf][am[i]][ak[i]]),
                       Ph + (long)am[i] * T_LEN + s0 + ak[i]);
#pragma unroll
        for (int i = 0; i < 2; i++)
            cp_async16(smem_u32(&Vs[buf][bd[i]][bk[i]]),
                       Vh + (long)bd[i] * T_LEN + s0 + bk[i]);
    };

    prefetch(0, 0); cp_commit();
    prefetch(1, 1); cp_commit();
    prefetch(2, 2); cp_commit();
    cp_wait<2>();
    __syncthreads();

    uint32_t aAddr[3][2], bAddr[3][2];
#pragma unroll
    for (int st = 0; st < 3; st++) {
#pragma unroll
        for (int i = 0; i < 2; i++)
            aAddr[st][i] = smem_u32(
                &Ps[st][wm0 + i*16 + (lane & 15)][(lane >> 4) * 8]);
#pragma unroll
        for (int jp = 0; jp < 2; jp++)
            bAddr[st][jp] = smem_u32(
                &Vs[st][wn0 + jp*16 + (lane & 7) + ((lane >> 4) << 3)]
                       [((lane >> 3) & 1) * 8]);
    }

    float acc[2][4][4];
#pragma unroll
    for (int i = 0; i < 2; i++)
#pragma unroll
        for (int j = 0; j < 4; j++)
#pragma unroll
            for (int q = 0; q < 4; q++) acc[i][j][q] = 0.0f;

#pragma unroll 1
    for (int it = 0; it < CTX_NI; ++it) {
        const int buf = it % 3;
#pragma unroll
        for (int ks = 0; ks < 4; ks++) {
            uint32_t af[2][4], bq[2][4];
#pragma unroll
            for (int i = 0; i < 2; i++) ldsm_x4(af[i], aAddr[buf][i] + ks * 32);
#pragma unroll
            for (int jp = 0; jp < 2; jp++) ldsm_x4(bq[jp], bAddr[buf][jp] + ks * 32);
#pragma unroll
            for (int i = 0; i < 2; i++)
#pragma unroll
                for (int j = 0; j < 4; j++)
                    mma_f16(acc[i][j], af[i][0], af[i][1], af[i][2], af[i][3],
                            bq[j >> 1][(j & 1) * 2], bq[j >> 1][(j & 1) * 2 + 1]);
        }
        __syncthreads();
        if (it + 3 < CTX_NI) { prefetch(it + 3, buf); cp_commit(); }
        if (it + 1 < CTX_NI) {
            if (it + 3 < CTX_NI)       cp_wait<2>();
            else if (it + 2 < CTX_NI)  cp_wait<1>();
            else                       cp_wait<0>();
            __syncthreads();
        }
    }

    const float* invh = inv + (long)h * T_LEN;
#pragma unroll
    for (int i = 0; i < 2; i++) {
#pragma unroll
        for (int j = 0; j < 4; j++) {
#pragma unroll
            for (int h2 = 0; h2 < 2; h2++) {
                const int m = gm0 + wm0 + i*16 + gid + h2*8;
                const int n = h * HD + wn0 + j*8 + tg*2;
                const float sc = invh[m];
                float v0 = acc[i][j][h2*2 + 0] * sc;
                float v1 = acc[i][j][h2*2 + 1] * sc;
                *(__half2*)(CTX + (long)m * E_DIM + n) = __floats2half2_rn(v0, v1);
            }
        }
    }
}

// ===========================================================================
// All-fp16 GEMM, 3-stage cp.async pipeline, BM=BN=128, BK=32, 256 thr (2x4).
//   C = (A @ B^T + bias) * scale
//   EPI 0: fp32 C[m*ldc+n]; 1: fp16 head-scatter [h][m][d]; 2: fp16 [h][d][m]
// ===========================================================================
template<int EPI>
__global__ __launch_bounds__(256, 2)
void gemm16_k(const __half* __restrict__ A, const __half* __restrict__ B,
              const float* __restrict__ bias, void* __restrict__ Cv,
              int M, int N, int K, int ldc, float scale)
{
    constexpr int BK = 32;
    __shared__ __half As[3][128][40];
    __shared__ __half Bs[3][128][40];
    constexpr uint32_t A_BUF = 128 * 40 * 2;
    constexpr uint32_t B_BUF = 128 * 40 * 2;

    const int tid  = threadIdx.x;
    const int warp = tid >> 5, lane = tid & 31;
    const int wm0 = (warp >> 2) * 64;   // WARPS_M=2 -> WM=64, MT=4
    const int wn0 = (warp & 3) * 32;    // WARPS_N=4 -> WN=32, NT=4
    const int gid = lane >> 2, tg = lane & 3;
    const int gm0 = blockIdx.y * 128, gn0 = blockIdx.x * 128;

    // 128x32 halfs per tile = 512 16B-chunks -> 2 per thread
    int am[2], ak[2];
#pragma unroll
    for (int i = 0; i < 2; i++) {
        const int idx = (tid + i * 256) * 8;
        am[i] = idx >> 5; ak[i] = idx & 31;
    }

    auto prefetch = [&](int it, int buf) {
        const int k0 = it * BK;
#pragma unroll
        for (int i = 0; i < 2; i++)
            cp_async16(smem_u32(&As[buf][am[i]][ak[i]]),
                       A + (long)(gm0 + am[i]) * K + k0 + ak[i]);
#pragma unroll
        for (int i = 0; i < 2; i++)
            cp_async16(smem_u32(&Bs[buf][am[i]][ak[i]]),
                       B + (long)(gn0 + am[i]) * K + k0 + ak[i]);
    };

    const int NI = K / BK;
    prefetch(0, 0); cp_commit();
    prefetch(1, 1); cp_commit();
    prefetch(2, 2); cp_commit();
    cp_wait<2>();
    __syncthreads();

    uint32_t aAddr0[4], bAddr0[2];
#pragma unroll
    for (int i = 0; i < 4; i++)
        aAddr0[i] = smem_u32(&As[0][wm0 + i*16 + (lane & 15)][(lane >> 4) * 8]);
#pragma unroll
    for (int jp = 0; jp < 2; jp++)
        bAddr0[jp] = smem_u32(&Bs[0][wn0 + jp*16 + (lane & 7) + ((lane >> 4) << 3)]
                                 [((lane >> 3) & 1) * 8]);

    float acc[4][4][4];
#pragma unroll
    for (int i = 0; i < 4; i++)
#pragma unroll
        for (int j = 0; j < 4; j++)
#pragma unroll
            for (int q = 0; q < 4; q++) acc[i][j][q] = 0.0f;

#pragma unroll 1
    for (int it = 0; it < NI; ++it) {
        const int buf = it % 3;
        const uint32_t aB = buf * A_BUF, bB = buf * B_BUF;
#pragma unroll
        for (int ks = 0; ks < BK; ks += 16) {
            uint32_t af[4][4], bq[2][4];
#pragma unroll
            for (int i = 0; i < 4; i++) ldsm_x4(af[i], aAddr0[i] + aB + ks * 2);
#pragma unroll
            for (int jp = 0; jp < 2; jp++) ldsm_x4(bq[jp], bAddr0[jp] + bB + ks * 2);
#pragma unroll
            for (int i = 0; i < 4; i++)
#pragma unroll
                for (int j = 0; j < 4; j++)
                    mma_f16(acc[i][j], af[i][0], af[i][1], af[i][2], af[i][3],
                            bq[j >> 1][(j & 1) * 2], bq[j >> 1][(j & 1) * 2 + 1]);
        }
        __syncthreads();
        if (it + 3 < NI) { prefetch(it + 3, buf); cp_commit(); }
        if (it + 1 < NI) {
            if (it + 3 < NI)       cp_wait<2>();
            else if (it + 2 < NI)  cp_wait<1>();
            else                   cp_wait<0>();
            __syncthreads();
        }
    }

    float*  Cf  = (float*)Cv;
    __half* Chp = (__half*)Cv;
#pragma unroll
    for (int i = 0; i < 4; i++) {
#pragma unroll
        for (int j = 0; j < 4; j++) {
#pragma unroll
            for (int h2 = 0; h2 < 2; h2++) {
                int m = gm0 + wm0 + i*16 + gid + h2*8;
                int n = gn0 + wn0 + j*8 + tg*2;
                float v0 = acc[i][j][h2*2 + 0];
                float v1 = acc[i][j][h2*2 + 1];
                if (bias) { v0 += bias[n]; v1 += bias[n+1]; }
                v0 *= scale; v1 *= scale;
                if (EPI == 0) {
                    *(float2*)(Cf + (long)m*ldc + n) = make_float2(v0, v1);
                } else if (EPI == 1) {          // [h][m][d]
                    int h = n >> 6, d = n & 63;
                    *(__half2*)(Chp + (long)h*M*HD + (long)m*HD + d) =
                        __floats2half2_rn(v0, v1);
                } else {                        // [h][d][m]
                    int h = n >> 6, d = n & 63;
                    __half* p = Chp + (long)h*HD*M + (long)d*M + m;
                    p[0] = __float2half_rn(v0);
                    p[M] = __float2half_rn(v1);
                }
            }
        }
    }
}

// ---------------------------------------------------------------------------
__global__ __launch_bounds__(256) void invred_k(const float* __restrict__ part,
                                                float* __restrict__ inv)
{
    const long row = (long)blockIdx.x * 256 + threadIdx.x;
    const float4 p = ((const float4*)part)[row];
    inv[row] = 1.0f / ((p.x + p.y) + (p.z + p.w));
}

// ---------------------------------------------------------------------------
__global__ __launch_bounds__(1024) void avg_k(const __half* __restrict__ P,
                                              const float* __restrict__ inv,
                                              float* __restrict__ out)
{
    const int t = blockIdx.x, tid = threadIdx.x;
    const long TS = (long)T_LEN * T_LEN;
    const __half* base = P + (long)t * T_LEN + tid * 4;
    float4 acc = make_float4(0.f, 0.f, 0.f, 0.f);
#pragma unroll
    for (int h = 0; h < H_NUM; h++) {
        const float iv = inv[h * T_LEN + t] * (1.0f / H_NUM);
        uint2 u = *(const uint2*)(base + (long)h * TS);
        float2 lo = __half22float2(*(__half2*)&u.x);
        float2 hi = __half22float2(*(__half2*)&u.y);
        acc.x += lo.x * iv; acc.y += lo.y * iv;
        acc.z += hi.x * iv; acc.w += hi.y * iv;
    }
    ((float4*)(out + (long)t * T_LEN))[tid] = acc;
}

// ---------------------------------------------------------------------------
extern "C" void kernel_launch(void* const* d_in, const int* in_sizes, int n_in,
                              void* d_out, int out_size)
{
    const float* q_in = (const float*)d_in[0];
    const float* k_in = (const float*)d_in[1];
    const float* v_in = (const float*)d_in[2];
    const float* w    = (const float*)d_in[3];
    const float* b    = (const float*)d_in[4];
    const float* ow   = (const float*)d_in[5];
    const float* ob   = (const float*)d_in[6];
    float* out = (float*)d_out;

    __half *Q, *K, *Vt, *P, *CTX, *X16, *W16;
    float *RSP, *INV;
    cudaGetSymbolAddress((void**)&Q,   g_Q);
    cudaGetSymbolAddress((void**)&K,   g_K);
    cudaGetSymbolAddress((void**)&Vt,  g_Vt);
    cudaGetSymbolAddress((void**)&P,   g_P);
    cudaGetSymbolAddress((void**)&CTX, g_CTX);
    cudaGetSymbolAddress((void**)&X16, g_X16);
    cudaGetSymbolAddress((void**)&W16, g_W16);
    cudaGetSymbolAddress((void**)&RSP, g_RSP);
    cudaGetSymbolAddress((void**)&INV, g_INV);

    const int T = T_LEN, E = E_DIM, H = H_NUM;
    const long EE = (long)E * E;
    const long TE = (long)T * E;
    dim3 blk(256);

    // fp32 -> fp16 conversions (numerically identical to old STS-time rounding)
    cvt_k<<<(int)(TE/4/256), 256>>>(q_in, X16);
    cvt_k<<<(int)(TE/4/256), 256>>>(k_in, X16 + TE);
    cvt_k<<<(int)(TE/4/256), 256>>>(v_in, X16 + 2*TE);
    cvt_k<<<(int)(3*EE/4/256), 256>>>(w,  W16);
    cvt_k<<<(int)(EE/4/256),   256>>>(ow, W16 + 3*EE);

    // QKV projections (all-fp16, cp.async pipeline)
    gemm16_k<1><<<dim3(E/128, T/128), blk>>>(
        X16,        W16,        b,       Q,   T, E, E, 0, 0.125f);
    gemm16_k<1><<<dim3(E/128, T/128), blk>>>(
        X16 + TE,   W16 + EE,   b + E,   K,   T, E, E, 0, 1.0f);
    gemm16_k<2><<<dim3(E/128, T/128), blk>>>(
        X16 + 2*TE, W16 + 2*EE, b + 2*E, Vt,  T, E, E, 0, 1.0f);

    // scores -> fp16 P + partial row sums
    scores_k<<<dim3(NBX_SCORES, T/128, H), blk>>>(Q, K, P, RSP);

    // row-sum reduce -> inv
    invred_k<<<(H*T)/256, 256>>>(RSP, INV);

    // head-average -> second half of d_out
    avg_k<<<T, 1024>>>(P, INV, out + (long)T * E);

    // ctx (dedicated pipelined kernel)
    ctx_k<<<dim3(T/128, H), blk>>>(P, Vt, INV, CTX);

    // out projection: fp16 CTX @ fp16 OW^T + bias -> fp32 out
    gemm16_k<0><<<dim3(E/128, T/128), blk>>>(
        CTX, W16 + 3*EE, ob, out, T, E, E, E, 1.0f);
}

// round 16
// speedup vs baseline: 1.0148x; 1.0120x over previous
#include <cuda_runtime.h>
#include <cuda_fp16.h>
#include <cstdint>

#define T_LEN 4096
#define E_DIM 1024
#define H_NUM 16
#define HD    64
#define NBX_SCORES 4
#define NT_SC 8

// Scratch (allocation-free rule: __device__ globals)
__device__ __half g_Q  [(long)H_NUM * T_LEN * HD];
__device__ __half g_K  [(long)H_NUM * T_LEN * HD];
__device__ __half g_Vt [(long)H_NUM * HD * T_LEN];
__device__ __half g_P  [(long)H_NUM * T_LEN * T_LEN];
__device__ __half g_CTX[(long)T_LEN * E_DIM];
__device__ __half g_X16[(long)3 * T_LEN * E_DIM];
__device__ __half g_W16[(long)4 * E_DIM * E_DIM];
__device__ float  g_RSP[(long)H_NUM * T_LEN * NBX_SCORES];
__device__ float  g_INV[(long)H_NUM * T_LEN];

__device__ __forceinline__ float ex2(float x) {
    float r;
    asm("ex2.approx.f32 %0, %1;" : "=f"(r) : "f"(x));
    return r;
}
__device__ __forceinline__ uint32_t smem_u32(const void* p) {
    return (uint32_t)__cvta_generic_to_shared(p);
}
__device__ __forceinline__ void ldsm_x4(uint32_t r[4], uint32_t addr) {
    asm volatile("ldmatrix.sync.aligned.m8n8.x4.shared.b16 {%0,%1,%2,%3}, [%4];"
        : "=r"(r[0]), "=r"(r[1]), "=r"(r[2]), "=r"(r[3]) : "r"(addr));
}
__device__ __forceinline__ void cp_async16(uint32_t saddr, const void* gaddr) {
    asm volatile("cp.async.cg.shared.global [%0], [%1], 16;" :: "r"(saddr), "l"(gaddr));
}
__device__ __forceinline__ void cp_commit() { asm volatile("cp.async.commit_group;"); }
template<int N>
__device__ __forceinline__ void cp_wait() {
    asm volatile("cp.async.wait_group %0;" :: "n"(N));
}

__device__ __forceinline__ void mma_f16(float c[4],
    uint32_t a0, uint32_t a1, uint32_t a2, uint32_t a3,
    uint32_t b0, uint32_t b1)
{
    asm volatile(
        "mma.sync.aligned.m16n8k16.row.col.f32.f16.f16.f32 "
        "{%0,%1,%2,%3}, {%4,%5,%6,%7}, {%8,%9}, {%0,%1,%2,%3};"
        : "+f"(c[0]), "+f"(c[1]), "+f"(c[2]), "+f"(c[3])
        : "r"(a0), "r"(a1), "r"(a2), "r"(a3), "r"(b0), "r"(b1));
}

#define LOG2E 1.4426950408889634f
#define PSHIFT 2.0f

// ---------------------------------------------------------------------------
// Merged fp32->fp16 convert: q|k|v|w|ow in one launch.
// Per block: 1024 floats. Ranges: 3x4096 (X), 3072 (w), 1024 (ow) = 16384.
// ---------------------------------------------------------------------------
__global__ __launch_bounds__(256) void cvt_all_k(
    const float* __restrict__ q, const float* __restrict__ k,
    const float* __restrict__ v, const float* __restrict__ w,
    const float* __restrict__ ow, __half* __restrict__ X16,
    __half* __restrict__ W16)
{
    const long TE = (long)T_LEN * E_DIM;
    const long EE = (long)E_DIM * E_DIM;
    int bx = blockIdx.x;
    const float* src; __half* dst;
    if (bx < 4096)        { src = q;  dst = X16;            }
    else if (bx < 8192)   { src = k;  dst = X16 + TE;       bx -= 4096; }
    else if (bx < 12288)  { src = v;  dst = X16 + 2*TE;     bx -= 8192; }
    else if (bx < 15360)  { src = w;  dst = W16;            bx -= 12288; }
    else                  { src = ow; dst = W16 + 3*EE;     bx -= 15360; }
    const long i = ((long)bx * 256 + threadIdx.x) * 4;
    float4 t = *(const float4*)(src + i);
    *(__half2*)(dst + i)     = __floats2half2_rn(t.x, t.y);
    *(__half2*)(dst + i + 2) = __floats2half2_rn(t.z, t.w);
}

// ===========================================================================
// Scores: 2-stage cp.async, Q frags in regs, STG.128 epilogue,
// hoisted u32 row offsets (this round's scores change).
// ===========================================================================
__global__ __launch_bounds__(256, 2)
void scores_k(const __half* __restrict__ Q, const __half* __restrict__ Kp,
              __half* __restrict__ P, float* __restrict__ rsp)
{
    __shared__ __half Qs[128][72];
    __shared__ __half Ks[2][128][72];
    __shared__ float  srs[512];

    const int tid  = threadIdx.x;
    const int warp = tid >> 5, lane = tid & 31;
    const int gid = lane >> 2, tg = lane & 3;
    const int wm0 = (warp >> 2) * 64;
    const int wn0 = (warp & 3) * 32;
    const int gm0 = blockIdx.y * 128;
    const int cbase = blockIdx.x * (NT_SC * 128);

    const __half* Ah = Q  + (long)blockIdx.z * T_LEN * HD + (long)gm0 * HD;
    const __half* Kh = Kp + (long)blockIdx.z * T_LEN * HD + (long)cbase * HD;

    int lm[4], lk[4];
#pragma unroll
    for (int i = 0; i < 4; i++) {
        const int idx = (tid + i * 256) * 8;
        lm[i] = idx >> 6; lk[i] = idx & 63;
    }
    auto prefetchK = [&](int nt, int buf) {
#pragma unroll
        for (int i = 0; i < 4; i++)
            cp_async16(smem_u32(&Ks[buf][lm[i]][lk[i]]),
                       Kh + ((long)nt * 128 + lm[i]) * HD + lk[i]);
    };

#pragma unroll
    for (int i = 0; i < 4; i++)
        cp_async16(smem_u32(&Qs[lm[i]][lk[i]]), Ah + (long)lm[i] * HD + lk[i]);
    prefetchK(0, 0); cp_commit();
    prefetchK(1, 1); cp_commit();
    cp_wait<1>();
    __syncthreads();

    uint32_t af[4][4][4];
#pragma unroll
    for (int i = 0; i < 4; i++) {
        const uint32_t a = smem_u32(&Qs[wm0 + i*16 + (lane & 15)][(lane >> 4) * 8]);
#pragma unroll
        for (int ks = 0; ks < 4; ks++) ldsm_x4(af[ks][i], a + ks * 32);
    }

    uint32_t bAddr[2][2];
#pragma unroll
    for (int buf = 0; buf < 2; buf++)
#pragma unroll
        for (int jp = 0; jp < 2; jp++)
            bAddr[buf][jp] = smem_u32(
                &Ks[buf][wn0 + jp*16 + (lane & 7) + ((lane >> 4) << 3)]
                        [((lane >> 3) & 1) * 8]);

    // hoisted row byte-offsets (P head slab is 32 MB -> fits u32)
    char* Chb = (char*)(P + (long)blockIdx.z * T_LEN * T_LEN);
    uint32_t roff[4][2];
#pragma unroll
    for (int i = 0; i < 4; i++)
#pragma unroll
        for (int h2 = 0; h2 < 2; h2++) {
            const int m = gm0 + wm0 + i * 16 + gid + h2 * 8;
            roff[i][h2] = (uint32_t)m * (T_LEN * 2) + (cbase + wn0 + tg * 8) * 2;
        }

    float rsum[4][2];
#pragma unroll
    for (int i = 0; i < 4; i++) { rsum[i][0] = 0.f; rsum[i][1] = 0.f; }

#pragma unroll 1
    for (int nt = 0; nt < NT_SC; nt++) {
        const int buf = nt & 1;

        float acc[4][4][4];
#pragma unroll
        for (int i = 0; i < 4; i++)
#pragma unroll
            for (int j = 0; j < 4; j++)
#pragma unroll
                for (int q = 0; q < 4; q++) acc[i][j][q] = 0.0f;

#pragma unroll
        for (int ks = 0; ks < 4; ks++) {
            uint32_t bq[2][4];
#pragma unroll
            for (int jp = 0; jp < 2; jp++)
                ldsm_x4(bq[jp], bAddr[buf][jp] + ks * 32);
#pragma unroll
            for (int i = 0; i < 4; i++)
#pragma unroll
                for (int j = 0; j < 4; j++)
                    mma_f16(acc[i][j], af[ks][i][0], af[ks][i][1],
                            af[ks][i][2], af[ks][i][3],
                            bq[j >> 1][(j & 1) * 2], bq[j >> 1][(j & 1) * 2 + 1]);
        }

        const uint32_t ntoff = (uint32_t)nt * 256;   // 128 halfs
#pragma unroll
        for (int i = 0; i < 4; i++) {
#pragma unroll
            for (int h2 = 0; h2 < 2; h2++) {
                uint32_t hp[4];
#pragma unroll
                for (int j = 0; j < 4; j++) {
                    float v0 = ex2(fmaf(acc[i][j][h2*2 + 0], LOG2E, PSHIFT));
                    float v1 = ex2(fmaf(acc[i][j][h2*2 + 1], LOG2E, PSHIFT));
                    rsum[i][h2] += v0 + v1;
                    __half2 h = __floats2half2_rn(v0, v1);
                    hp[j] = *(uint32_t*)&h;
                }
                {
                    uint32_t t, r;
                    t = (tg & 1) ? hp[0] : hp[1];
                    r = __shfl_xor_sync(0xffffffffu, t, 1);
                    if (tg & 1) hp[0] = r; else hp[1] = r;
                    t = (tg & 1) ? hp[2] : hp[3];
                    r = __shfl_xor_sync(0xffffffffu, t, 1);
                    if (tg & 1) hp[2] = r; else hp[3] = r;
                    t = (tg & 2) ? hp[0] : hp[2];
                    r = __shfl_xor_sync(0xffffffffu, t, 2);
                    if (tg & 2) hp[0] = r; else hp[2] = r;
                    t = (tg & 2) ? hp[1] : hp[3];
                    r = __shfl_xor_sync(0xffffffffu, t, 2);
                    if (tg & 2) hp[1] = r; else hp[3] = r;
                }
                *(uint4*)(Chb + roff[i][h2] + ntoff) =
                    make_uint4(hp[0], hp[1], hp[2], hp[3]);
            }
        }

        __syncthreads();
        if (nt + 2 < NT_SC) { prefetchK(nt + 2, buf); cp_commit(); }
        if (nt + 1 < NT_SC) {
            if (nt + 2 < NT_SC) cp_wait<1>(); else cp_wait<0>();
            __syncthreads();
        }
    }

#pragma unroll
    for (int i = 0; i < 4; i++)
#pragma unroll
        for (int h2 = 0; h2 < 2; h2++)
#pragma unroll
            for (int o = 1; o < 4; o <<= 1)
                rsum[i][h2] += __shfl_xor_sync(0xffffffffu, rsum[i][h2], o);
    if (tg == 0) {
        const int wn = warp & 3;
#pragma unroll
        for (int i = 0; i < 4; i++)
#pragma unroll
            for (int h2 = 0; h2 < 2; h2++)
                srs[wn * 128 + wm0 + i * 16 + h2 * 8 + gid] = rsum[i][h2];
    }
    __syncthreads();
    if (tid < 128) {
        float s = srs[tid] + srs[128 + tid] + srs[256 + tid] + srs[384 + tid];
        rsp[((long)blockIdx.z * T_LEN + gm0 + tid) * NBX_SCORES + blockIdx.x] = s;
    }
}

// ===========================================================================
// Dedicated ctx kernel (unchanged).
// ===========================================================================
#define CTX_BK 64
#define CTX_NI (T_LEN / CTX_BK)

__global__ __launch_bounds__(256, 2)
void ctx_k(const __half* __restrict__ P, const __half* __restrict__ Vt,
           const float* __restrict__ inv, __half* __restrict__ CTX)
{
    __shared__ __half Ps[3][128][72];
    __shared__ __half Vs[3][64][72];

    const int tid  = threadIdx.x;
    const int warp = tid >> 5, lane = tid & 31;
    const int gid = lane >> 2, tg = lane & 3;
    const int wm0 = (warp >> 1) * 32;
    const int wn0 = (warp & 1) * 32;
    const int gm0 = blockIdx.x * 128;
    const int h   = blockIdx.y;

    const __half* Ph = P  + (long)h * T_LEN * T_LEN + (long)gm0 * T_LEN;
    const __half* Vh = Vt + (long)h * HD * T_LEN;

    int am[4], ak[4], bd[2], bk[2];
#pragma unroll
    for (int i = 0; i < 4; i++) {
        const int idx = (tid + i * 256) * 8;
        am[i] = idx >> 6; ak[i] = idx & 63;
    }
#pragma unroll
    for (int i = 0; i < 2; i++) {
        const int idx = (tid + i * 256) * 8;
        bd[i] = idx >> 6; bk[i] = idx & 63;
    }

    auto prefetch = [&](int it, int buf) {
        const int s0 = it * CTX_BK;
#pragma unroll
        for (int i = 0; i < 4; i++)
            cp_async16(smem_u32(&Ps[buf][am[i]][ak[i]]),
                       Ph + (long)am[i] * T_LEN + s0 + ak[i]);
#pragma unroll
        for (int i = 0; i < 2; i++)
            cp_async16(smem_u32(&Vs[buf][bd[i]][bk[i]]),
                       Vh + (long)bd[i] * T_LEN + s0 + bk[i]);
    };

    prefetch(0, 0); cp_commit();
    prefetch(1, 1); cp_commit();
    prefetch(2, 2); cp_commit();
    cp_wait<2>();
    __syncthreads();

    uint32_t aAddr[3][2], bAddr[3][2];
#pragma unroll
    for (int st = 0; st < 3; st++) {
#pragma unroll
        for (int i = 0; i < 2; i++)
            aAddr[st][i] = smem_u32(
                &Ps[st][wm0 + i*16 + (lane & 15)][(lane >> 4) * 8]);
#pragma unroll
        for (int jp = 0; jp < 2; jp++)
            bAddr[st][jp] = smem_u32(
                &Vs[st][wn0 + jp*16 + (lane & 7) + ((lane >> 4) << 3)]
                       [((lane >> 3) & 1) * 8]);
    }

    float acc[2][4][4];
#pragma unroll
    for (int i = 0; i < 2; i++)
#pragma unroll
        for (int j = 0; j < 4; j++)
#pragma unroll
            for (int q = 0; q < 4; q++) acc[i][j][q] = 0.0f;

#pragma unroll 1
    for (int it = 0; it < CTX_NI; ++it) {
        const int buf = it % 3;
#pragma unroll
        for (int ks = 0; ks < 4; ks++) {
            uint32_t af[2][4], bq[2][4];
#pragma unroll
            for (int i = 0; i < 2; i++) ldsm_x4(af[i], aAddr[buf][i] + ks * 32);
#pragma unroll
            for (int jp = 0; jp < 2; jp++) ldsm_x4(bq[jp], bAddr[buf][jp] + ks * 32);
#pragma unroll
            for (int i = 0; i < 2; i++)
#pragma unroll
                for (int j = 0; j < 4; j++)
                    mma_f16(acc[i][j], af[i][0], af[i][1], af[i][2], af[i][3],
                            bq[j >> 1][(j & 1) * 2], bq[j >> 1][(j & 1) * 2 + 1]);
        }
        __syncthreads();
        if (it + 3 < CTX_NI) { prefetch(it + 3, buf); cp_commit(); }
        if (it + 1 < CTX_NI) {
            if (it + 3 < CTX_NI)       cp_wait<2>();
            else if (it + 2 < CTX_NI)  cp_wait<1>();
            else                       cp_wait<0>();
            __syncthreads();
        }
    }

    const float* invh = inv + (long)h * T_LEN;
#pragma unroll
    for (int i = 0; i < 2; i++) {
#pragma unroll
        for (int j = 0; j < 4; j++) {
#pragma unroll
            for (int h2 = 0; h2 < 2; h2++) {
                const int m = gm0 + wm0 + i*16 + gid + h2*8;
                const int n = h * HD + wn0 + j*8 + tg*2;
                const float sc = invh[m];
                float v0 = acc[i][j][h2*2 + 0] * sc;
                float v1 = acc[i][j][h2*2 + 1] * sc;
                *(__half2*)(CTX + (long)m * E_DIM + n) = __floats2half2_rn(v0, v1);
            }
        }
    }
}

// ===========================================================================
// Merged QKV projection GEMM: grid (E/128, T/128, 3).
// z=0: Q (scale 0.125, EPI head [h][m][d]); z=1: K (EPI head);
// z=2: V -> Vt (EPI [h][d][m]). All-fp16, 3-stage cp.async, K=E_DIM.
// ===========================================================================
__global__ __launch_bounds__(256, 2)
void qkv_k(const __half* __restrict__ X16, const __half* __restrict__ W16,
           const float* __restrict__ bias3,
           __half* __restrict__ Q, __half* __restrict__ Kq,
           __half* __restrict__ Vt)
{
    constexpr int BK = 32;
    constexpr int KD = E_DIM;
    __shared__ __half As[3][128][40];
    __shared__ __half Bs[3][128][40];
    constexpr uint32_t A_BUF = 128 * 40 * 2;
    constexpr uint32_t B_BUF = 128 * 40 * 2;

    const int z = blockIdx.z;
    const __half* A = X16 + (long)z * T_LEN * E_DIM;
    const __half* B = W16 + (long)z * E_DIM * E_DIM;
    const float* bias = bias3 + z * E_DIM;
    __half* C = (z == 0) ? Q : (z == 1) ? Kq : Vt;
    const float scale = (z == 0) ? 0.125f : 1.0f;

    const int tid  = threadIdx.x;
    const int warp = tid >> 5, lane = tid & 31;
    const int wm0 = (warp >> 2) * 64;
    const int wn0 = (warp & 3) * 32;
    const int gid = lane >> 2, tg = lane & 3;
    const int gm0 = blockIdx.y * 128, gn0 = blockIdx.x * 128;

    int am[2], ak[2];
#pragma unroll
    for (int i = 0; i < 2; i++) {
        const int idx = (tid + i * 256) * 8;
        am[i] = idx >> 5; ak[i] = idx & 31;
    }

    auto prefetch = [&](int it, int buf) {
        const int k0 = it * BK;
#pragma unroll
        for (int i = 0; i < 2; i++)
            cp_async16(smem_u32(&As[buf][am[i]][ak[i]]),
                       A + (long)(gm0 + am[i]) * KD + k0 + ak[i]);
#pragma unroll
        for (int i = 0; i < 2; i++)
            cp_async16(smem_u32(&Bs[buf][am[i]][ak[i]]),
                       B + (long)(gn0 + am[i]) * KD + k0 + ak[i]);
    };

    const int NI = KD / BK;
    prefetch(0, 0); cp_commit();
    prefetch(1, 1); cp_commit();
    prefetch(2, 2); cp_commit();
    cp_wait<2>();
    __syncthreads();

    uint32_t aAddr0[4], bAddr0[2];
#pragma unroll
    for (int i = 0; i < 4; i++)
        aAddr0[i] = smem_u32(&As[0][wm0 + i*16 + (lane & 15)][(lane >> 4) * 8]);
#pragma unroll
    for (int jp = 0; jp < 2; jp++)
        bAddr0[jp] = smem_u32(&Bs[0][wn0 + jp*16 + (lane & 7) + ((lane >> 4) << 3)]
                                 [((lane >> 3) & 1) * 8]);

    float acc[4][4][4];
#pragma unroll
    for (int i = 0; i < 4; i++)
#pragma unroll
        for (int j = 0; j < 4; j++)
#pragma unroll
            for (int q = 0; q < 4; q++) acc[i][j][q] = 0.0f;

#pragma unroll 1
    for (int it = 0; it < NI; ++it) {
        const int buf = it % 3;
        const uint32_t aB = buf * A_BUF, bB = buf * B_BUF;
#pragma unroll
        for (int ks = 0; ks < BK; ks += 16) {
            uint32_t af[4][4], bq[2][4];
#pragma unroll
            for (int i = 0; i < 4; i++) ldsm_x4(af[i], aAddr0[i] + aB + ks * 2);
#pragma unroll
            for (int jp = 0; jp < 2; jp++) ldsm_x4(bq[jp], bAddr0[jp] + bB + ks * 2);
#pragma unroll
            for (int i = 0; i < 4; i++)
#pragma unroll
                for (int j = 0; j < 4; j++)
                    mma_f16(acc[i][j], af[i][0], af[i][1], af[i][2], af[i][3],
                            bq[j >> 1][(j & 1) * 2], bq[j >> 1][(j & 1) * 2 + 1]);
        }
        __syncthreads();
        if (it + 3 < NI) { prefetch(it + 3, buf); cp_commit(); }
        if (it + 1 < NI) {
            if (it + 3 < NI)       cp_wait<2>();
            else if (it + 2 < NI)  cp_wait<1>();
            else                   cp_wait<0>();
            __syncthreads();
        }
    }

#pragma unroll
    for (int i = 0; i < 4; i++) {
#pragma unroll
        for (int j = 0; j < 4; j++) {
#pragma unroll
            for (int h2 = 0; h2 < 2; h2++) {
                int m = gm0 + wm0 + i*16 + gid + h2*8;
                int n = gn0 + wn0 + j*8 + tg*2;
                float v0 = (acc[i][j][h2*2 + 0] + bias[n])   * scale;
                float v1 = (acc[i][j][h2*2 + 1] + bias[n+1]) * scale;
                int h = n >> 6, d = n & 63;
                if (z < 2) {                     // [h][m][d]
                    *(__half2*)(C + (long)h*T_LEN*HD + (long)m*HD + d) =
                        __floats2half2_rn(v0, v1);
                } else {                         // [h][d][m]
                    __half* p = C + (long)h*HD*T_LEN + (long)d*T_LEN + m;
                    p[0]     = __float2half_rn(v0);
                    p[T_LEN] = __float2half_rn(v1);
                }
            }
        }
    }
}

// ===========================================================================
// Out-projection GEMM (all-fp16, fp32 out), unchanged from R15 (EPI 0 only).
// ===========================================================================
__global__ __launch_bounds__(256, 2)
void outproj_k(const __half* __restrict__ A, const __half* __restrict__ B,
               const float* __restrict__ bias, float* __restrict__ C)
{
    constexpr int BK = 32;
    constexpr int KD = E_DIM;
    __shared__ __half As[3][128][40];
    __shared__ __half Bs[3][128][40];
    constexpr uint32_t A_BUF = 128 * 40 * 2;
    constexpr uint32_t B_BUF = 128 * 40 * 2;

    const int tid  = threadIdx.x;
    const int warp = tid >> 5, lane = tid & 31;
    const int wm0 = (warp >> 2) * 64;
    const int wn0 = (warp & 3) * 32;
    const int gid = lane >> 2, tg = lane & 3;
    const int gm0 = blockIdx.y * 128, gn0 = blockIdx.x * 128;

    int am[2], ak[2];
#pragma unroll
    for (int i = 0; i < 2; i++) {
        const int idx = (tid + i * 256) * 8;
        am[i] = idx >> 5; ak[i] = idx & 31;
    }

    auto prefetch = [&](int it, int buf) {
        const int k0 = it * BK;
#pragma unroll
        for (int i = 0; i < 2; i++)
            cp_async16(smem_u32(&As[buf][am[i]][ak[i]]),
                       A + (long)(gm0 + am[i]) * KD + k0 + ak[i]);
#pragma unroll
        for (int i = 0; i < 2; i++)
            cp_async16(smem_u32(&Bs[buf][am[i]][ak[i]]),
                       B + (long)(gn0 + am[i]) * KD + k0 + ak[i]);
    };

    const int NI = KD / BK;
    prefetch(0, 0); cp_commit();
    prefetch(1, 1); cp_commit();
    prefetch(2, 2); cp_commit();
    cp_wait<2>();
    __syncthreads();

    uint32_t aAddr0[4], bAddr0[2];
#pragma unroll
    for (int i = 0; i < 4; i++)
        aAddr0[i] = smem_u32(&As[0][wm0 + i*16 + (lane & 15)][(lane >> 4) * 8]);
#pragma unroll
    for (int jp = 0; jp < 2; jp++)
        bAddr0[jp] = smem_u32(&Bs[0][wn0 + jp*16 + (lane & 7) + ((lane >> 4) << 3)]
                                 [((lane >> 3) & 1) * 8]);

    float acc[4][4][4];
#pragma unroll
    for (int i = 0; i < 4; i++)
#pragma unroll
        for (int j = 0; j < 4; j++)
#pragma unroll
            for (int q = 0; q < 4; q++) acc[i][j][q] = 0.0f;

#pragma unroll 1
    for (int it = 0; it < NI; ++it) {
        const int buf = it % 3;
        const uint32_t aB = buf * A_BUF, bB = buf * B_BUF;
#pragma unroll
        for (int ks = 0; ks < BK; ks += 16) {
            uint32_t af[4][4], bq[2][4];
#pragma unroll
            for (int i = 0; i < 4; i++) ldsm_x4(af[i], aAddr0[i] + aB + ks * 2);
#pragma unroll
            for (int jp = 0; jp < 2; jp++) ldsm_x4(bq[jp], bAddr0[jp] + bB + ks * 2);
#pragma unroll
            for (int i = 0; i < 4; i++)
#pragma unroll
                for (int j = 0; j < 4; j++)
                    mma_f16(acc[i][j], af[i][0], af[i][1], af[i][2], af[i][3],
                            bq[j >> 1][(j & 1) * 2], bq[j >> 1][(j & 1) * 2 + 1]);
        }
        __syncthreads();
        if (it + 3 < NI) { prefetch(it + 3, buf); cp_commit(); }
        if (it + 1 < NI) {
            if (it + 3 < NI)       cp_wait<2>();
            else if (it + 2 < NI)  cp_wait<1>();
            else                   cp_wait<0>();
            __syncthreads();
        }
    }

#pragma unroll
    for (int i = 0; i < 4; i++) {
#pragma unroll
        for (int j = 0; j < 4; j++) {
#pragma unroll
            for (int h2 = 0; h2 < 2; h2++) {
                int m = gm0 + wm0 + i*16 + gid + h2*8;
                int n = gn0 + wn0 + j*8 + tg*2;
                float v0 = acc[i][j][h2*2 + 0] + bias[n];
                float v1 = acc[i][j][h2*2 + 1] + bias[n+1];
                *(float2*)(C + (long)m*E_DIM + n) = make_float2(v0, v1);
            }
        }
    }
}

// ---------------------------------------------------------------------------
__global__ __launch_bounds__(256) void invred_k(const float* __restrict__ part,
                                                float* __restrict__ inv)
{
    const long row = (long)blockIdx.x * 256 + threadIdx.x;
    const float4 p = ((const float4*)part)[row];
    inv[row] = 1.0f / ((p.x + p.y) + (p.z + p.w));
}

// ---------------------------------------------------------------------------
__global__ __launch_bounds__(1024) void avg_k(const __half* __restrict__ P,
                                              const float* __restrict__ inv,
                                              float* __restrict__ out)
{
    const int t = blockIdx.x, tid = threadIdx.x;
    const long TS = (long)T_LEN * T_LEN;
    const __half* base = P + (long)t * T_LEN + tid * 4;
    float4 acc = make_float4(0.f, 0.f, 0.f, 0.f);
#pragma unroll
    for (int h = 0; h < H_NUM; h++) {
        const float iv = inv[h * T_LEN + t] * (1.0f / H_NUM);
        uint2 u = *(const uint2*)(base + (long)h * TS);
        float2 lo = __half22float2(*(__half2*)&u.x);
        float2 hi = __half22float2(*(__half2*)&u.y);
        acc.x += lo.x * iv; acc.y += lo.y * iv;
        acc.z += hi.x * iv; acc.w += hi.y * iv;
    }
    ((float4*)(out + (long)t * T_LEN))[tid] = acc;
}

// ---------------------------------------------------------------------------
extern "C" void kernel_launch(void* const* d_in, const int* in_sizes, int n_in,
                              void* d_out, int out_size)
{
    const float* q_in = (const float*)d_in[0];
    const float* k_in = (const float*)d_in[1];
    const float* v_in = (const float*)d_in[2];
    const float* w    = (const float*)d_in[3];
    const float* b    = (const float*)d_in[4];
    const float* ow   = (const float*)d_in[5];
    const float* ob   = (const float*)d_in[6];
    float* out = (float*)d_out;

    __half *Q, *K, *Vt, *P, *CTX, *X16, *W16;
    float *RSP, *INV;
    cudaGetSymbolAddress((void**)&Q,   g_Q);
    cudaGetSymbolAddress((void**)&K,   g_K);
    cudaGetSymbolAddress((void**)&Vt,  g_Vt);
    cudaGetSymbolAddress((void**)&P,   g_P);
    cudaGetSymbolAddress((void**)&CTX, g_CTX);
    cudaGetSymbolAddress((void**)&X16, g_X16);
    cudaGetSymbolAddress((void**)&W16, g_W16);
    cudaGetSymbolAddress((void**)&RSP, g_RSP);
    cudaGetSymbolAddress((void**)&INV, g_INV);

    const int T = T_LEN, E = E_DIM, H = H_NUM;
    const long EE = (long)E * E;
    dim3 blk(256);

    // single merged fp32->fp16 conversion
    cvt_all_k<<<16384, 256>>>(q_in, k_in, v_in, w, ow, X16, W16);

    // merged QKV projections (grid.z selects q/k/v)
    qkv_k<<<dim3(E/128, T/128, 3), blk>>>(X16, W16, b, Q, K, Vt);

    // scores -> fp16 P + partial row sums
    scores_k<<<dim3(NBX_SCORES, T/128, H), blk>>>(Q, K, P, RSP);

    // row-sum reduce -> inv
    invred_k<<<(H*T)/256, 256>>>(RSP, INV);

    // head-average -> second half of d_out
    avg_k<<<T, 1024>>>(P, INV, out + (long)T * E);

    // ctx (dedicated pipelined kernel)
    ctx_k<<<dim3(T/128, H), blk>>>(P, Vt, INV, CTX);

    // out projection
    outproj_k<<<dim3(E/128, T/128), blk>>>(CTX, W16 + 3*EE, ob, out);
}

// round 17
// speedup vs baseline: 1.0208x; 1.0059x over previous
#include <cuda_runtime.h>
#include <cuda_fp16.h>
#include <cstdint>

#define T_LEN 4096
#define E_DIM 1024
#define H_NUM 16
#define HD    64
#define NBX_SCORES 4
#define NT_SC 8

// Scratch (allocation-free rule: __device__ globals)
__device__ __half g_Q  [(long)H_NUM * T_LEN * HD];
__device__ __half g_K  [(long)H_NUM * T_LEN * HD];
__device__ __half g_Vt [(long)H_NUM * HD * T_LEN];
__device__ __half g_P  [(long)H_NUM * T_LEN * T_LEN];
__device__ __half g_CTX[(long)T_LEN * E_DIM];
__device__ __half g_X16[(long)3 * T_LEN * E_DIM];
__device__ __half g_W16[(long)4 * E_DIM * E_DIM];
__device__ float  g_RSP[(long)H_NUM * T_LEN * NBX_SCORES];
__device__ float  g_INV[(long)H_NUM * T_LEN];

__device__ __forceinline__ float ex2(float x) {
    float r;
    asm("ex2.approx.f32 %0, %1;" : "=f"(r) : "f"(x));
    return r;
}
__device__ __forceinline__ uint32_t smem_u32(const void* p) {
    return (uint32_t)__cvta_generic_to_shared(p);
}
__device__ __forceinline__ void ldsm_x4(uint32_t r[4], uint32_t addr) {
    asm volatile("ldmatrix.sync.aligned.m8n8.x4.shared.b16 {%0,%1,%2,%3}, [%4];"
        : "=r"(r[0]), "=r"(r[1]), "=r"(r[2]), "=r"(r[3]) : "r"(addr));
}
__device__ __forceinline__ void cp_async16(uint32_t saddr, const void* gaddr) {
    asm volatile("cp.async.cg.shared.global [%0], [%1], 16;" :: "r"(saddr), "l"(gaddr));
}
__device__ __forceinline__ void cp_commit() { asm volatile("cp.async.commit_group;"); }
template<int N>
__device__ __forceinline__ void cp_wait() {
    asm volatile("cp.async.wait_group %0;" :: "n"(N));
}

__device__ __forceinline__ void mma_f16(float c[4],
    uint32_t a0, uint32_t a1, uint32_t a2, uint32_t a3,
    uint32_t b0, uint32_t b1)
{
    asm volatile(
        "mma.sync.aligned.m16n8k16.row.col.f32.f16.f16.f32 "
        "{%0,%1,%2,%3}, {%4,%5,%6,%7}, {%8,%9}, {%0,%1,%2,%3};"
        : "+f"(c[0]), "+f"(c[1]), "+f"(c[2]), "+f"(c[3])
        : "r"(a0), "r"(a1), "r"(a2), "r"(a3), "r"(b0), "r"(b1));
}

#define LOG2E 1.4426950408889634f
#define PSHIFT 2.0f

// ---------------------------------------------------------------------------
// Merged fp32->fp16 convert: q|k|v|w|ow in one launch.
// ---------------------------------------------------------------------------
__global__ __launch_bounds__(256) void cvt_all_k(
    const float* __restrict__ q, const float* __restrict__ k,
    const float* __restrict__ v, const float* __restrict__ w,
    const float* __restrict__ ow, __half* __restrict__ X16,
    __half* __restrict__ W16)
{
    const long TE = (long)T_LEN * E_DIM;
    const long EE = (long)E_DIM * E_DIM;
    int bx = blockIdx.x;
    const float* src; __half* dst;
    if (bx < 4096)        { src = q;  dst = X16;            }
    else if (bx < 8192)   { src = k;  dst = X16 + TE;       bx -= 4096; }
    else if (bx < 12288)  { src = v;  dst = X16 + 2*TE;     bx -= 8192; }
    else if (bx < 15360)  { src = w;  dst = W16;            bx -= 12288; }
    else                  { src = ow; dst = W16 + 3*EE;     bx -= 15360; }
    const long i = ((long)bx * 256 + threadIdx.x) * 4;
    float4 t = *(const float4*)(src + i);
    *(__half2*)(dst + i)     = __floats2half2_rn(t.x, t.y);
    *(__half2*)(dst + i + 2) = __floats2half2_rn(t.z, t.w);
}

// ===========================================================================
// Scores (R16, unchanged).
// ===========================================================================
__global__ __launch_bounds__(256, 2)
void scores_k(const __half* __restrict__ Q, const __half* __restrict__ Kp,
              __half* __restrict__ P, float* __restrict__ rsp)
{
    __shared__ __half Qs[128][72];
    __shared__ __half Ks[2][128][72];
    __shared__ float  srs[512];

    const int tid  = threadIdx.x;
    const int warp = tid >> 5, lane = tid & 31;
    const int gid = lane >> 2, tg = lane & 3;
    const int wm0 = (warp >> 2) * 64;
    const int wn0 = (warp & 3) * 32;
    const int gm0 = blockIdx.y * 128;
    const int cbase = blockIdx.x * (NT_SC * 128);

    const __half* Ah = Q  + (long)blockIdx.z * T_LEN * HD + (long)gm0 * HD;
    const __half* Kh = Kp + (long)blockIdx.z * T_LEN * HD + (long)cbase * HD;

    int lm[4], lk[4];
#pragma unroll
    for (int i = 0; i < 4; i++) {
        const int idx = (tid + i * 256) * 8;
        lm[i] = idx >> 6; lk[i] = idx & 63;
    }
    auto prefetchK = [&](int nt, int buf) {
#pragma unroll
        for (int i = 0; i < 4; i++)
            cp_async16(smem_u32(&Ks[buf][lm[i]][lk[i]]),
                       Kh + ((long)nt * 128 + lm[i]) * HD + lk[i]);
    };

#pragma unroll
    for (int i = 0; i < 4; i++)
        cp_async16(smem_u32(&Qs[lm[i]][lk[i]]), Ah + (long)lm[i] * HD + lk[i]);
    prefetchK(0, 0); cp_commit();
    prefetchK(1, 1); cp_commit();
    cp_wait<1>();
    __syncthreads();

    uint32_t af[4][4][4];
#pragma unroll
    for (int i = 0; i < 4; i++) {
        const uint32_t a = smem_u32(&Qs[wm0 + i*16 + (lane & 15)][(lane >> 4) * 8]);
#pragma unroll
        for (int ks = 0; ks < 4; ks++) ldsm_x4(af[ks][i], a + ks * 32);
    }

    uint32_t bAddr[2][2];
#pragma unroll
    for (int buf = 0; buf < 2; buf++)
#pragma unroll
        for (int jp = 0; jp < 2; jp++)
            bAddr[buf][jp] = smem_u32(
                &Ks[buf][wn0 + jp*16 + (lane & 7) + ((lane >> 4) << 3)]
                        [((lane >> 3) & 1) * 8]);

    char* Chb = (char*)(P + (long)blockIdx.z * T_LEN * T_LEN);
    uint32_t roff[4][2];
#pragma unroll
    for (int i = 0; i < 4; i++)
#pragma unroll
        for (int h2 = 0; h2 < 2; h2++) {
            const int m = gm0 + wm0 + i * 16 + gid + h2 * 8;
            roff[i][h2] = (uint32_t)m * (T_LEN * 2) + (cbase + wn0 + tg * 8) * 2;
        }

    float rsum[4][2];
#pragma unroll
    for (int i = 0; i < 4; i++) { rsum[i][0] = 0.f; rsum[i][1] = 0.f; }

#pragma unroll 1
    for (int nt = 0; nt < NT_SC; nt++) {
        const int buf = nt & 1;

        float acc[4][4][4];
#pragma unroll
        for (int i = 0; i < 4; i++)
#pragma unroll
            for (int j = 0; j < 4; j++)
#pragma unroll
                for (int q = 0; q < 4; q++) acc[i][j][q] = 0.0f;

#pragma unroll
        for (int ks = 0; ks < 4; ks++) {
            uint32_t bq[2][4];
#pragma unroll
            for (int jp = 0; jp < 2; jp++)
                ldsm_x4(bq[jp], bAddr[buf][jp] + ks * 32);
#pragma unroll
            for (int i = 0; i < 4; i++)
#pragma unroll
                for (int j = 0; j < 4; j++)
                    mma_f16(acc[i][j], af[ks][i][0], af[ks][i][1],
                            af[ks][i][2], af[ks][i][3],
                            bq[j >> 1][(j & 1) * 2], bq[j >> 1][(j & 1) * 2 + 1]);
        }

        const uint32_t ntoff = (uint32_t)nt * 256;
#pragma unroll
        for (int i = 0; i < 4; i++) {
#pragma unroll
            for (int h2 = 0; h2 < 2; h2++) {
                uint32_t hp[4];
#pragma unroll
                for (int j = 0; j < 4; j++) {
                    float v0 = ex2(fmaf(acc[i][j][h2*2 + 0], LOG2E, PSHIFT));
                    float v1 = ex2(fmaf(acc[i][j][h2*2 + 1], LOG2E, PSHIFT));
                    rsum[i][h2] += v0 + v1;
                    __half2 h = __floats2half2_rn(v0, v1);
                    hp[j] = *(uint32_t*)&h;
                }
                {
                    uint32_t t, r;
                    t = (tg & 1) ? hp[0] : hp[1];
                    r = __shfl_xor_sync(0xffffffffu, t, 1);
                    if (tg & 1) hp[0] = r; else hp[1] = r;
                    t = (tg & 1) ? hp[2] : hp[3];
                    r = __shfl_xor_sync(0xffffffffu, t, 1);
                    if (tg & 1) hp[2] = r; else hp[3] = r;
                    t = (tg & 2) ? hp[0] : hp[2];
                    r = __shfl_xor_sync(0xffffffffu, t, 2);
                    if (tg & 2) hp[0] = r; else hp[2] = r;
                    t = (tg & 2) ? hp[1] : hp[3];
                    r = __shfl_xor_sync(0xffffffffu, t, 2);
                    if (tg & 2) hp[1] = r; else hp[3] = r;
                }
                *(uint4*)(Chb + roff[i][h2] + ntoff) =
                    make_uint4(hp[0], hp[1], hp[2], hp[3]);
            }
        }

        __syncthreads();
        if (nt + 2 < NT_SC) { prefetchK(nt + 2, buf); cp_commit(); }
        if (nt + 1 < NT_SC) {
            if (nt + 2 < NT_SC) cp_wait<1>(); else cp_wait<0>();
            __syncthreads();
        }
    }

#pragma unroll
    for (int i = 0; i < 4; i++)
#pragma unroll
        for (int h2 = 0; h2 < 2; h2++)
#pragma unroll
            for (int o = 1; o < 4; o <<= 1)
                rsum[i][h2] += __shfl_xor_sync(0xffffffffu, rsum[i][h2], o);
    if (tg == 0) {
        const int wn = warp & 3;
#pragma unroll
        for (int i = 0; i < 4; i++)
#pragma unroll
            for (int h2 = 0; h2 < 2; h2++)
                srs[wn * 128 + wm0 + i * 16 + h2 * 8 + gid] = rsum[i][h2];
    }
    __syncthreads();
    if (tid < 128) {
        float s = srs[tid] + srs[128 + tid] + srs[256 + tid] + srs[384 + tid];
        rsp[((long)blockIdx.z * T_LEN + gm0 + tid) * NBX_SCORES + blockIdx.x] = s;
    }
}

// ===========================================================================
// Dedicated ctx kernel (unchanged).
// ===========================================================================
#define CTX_BK 64
#define CTX_NI (T_LEN / CTX_BK)

__global__ __launch_bounds__(256, 2)
void ctx_k(const __half* __restrict__ P, const __half* __restrict__ Vt,
           const float* __restrict__ inv, __half* __restrict__ CTX)
{
    __shared__ __half Ps[3][128][72];
    __shared__ __half Vs[3][64][72];

    const int tid  = threadIdx.x;
    const int warp = tid >> 5, lane = tid & 31;
    const int gid = lane >> 2, tg = lane & 3;
    const int wm0 = (warp >> 1) * 32;
    const int wn0 = (warp & 1) * 32;
    const int gm0 = blockIdx.x * 128;
    const int h   = blockIdx.y;

    const __half* Ph = P  + (long)h * T_LEN * T_LEN + (long)gm0 * T_LEN;
    const __half* Vh = Vt + (long)h * HD * T_LEN;

    int am[4], ak[4], bd[2], bk[2];
#pragma unroll
    for (int i = 0; i < 4; i++) {
        const int idx = (tid + i * 256) * 8;
        am[i] = idx >> 6; ak[i] = idx & 63;
    }
#pragma unroll
    for (int i = 0; i < 2; i++) {
        const int idx = (tid + i * 256) * 8;
        bd[i] = idx >> 6; bk[i] = idx & 63;
    }

    auto prefetch = [&](int it, int buf) {
        const int s0 = it * CTX_BK;
#pragma unroll
        for (int i = 0; i < 4; i++)
            cp_async16(smem_u32(&Ps[buf][am[i]][ak[i]]),
                       Ph + (long)am[i] * T_LEN + s0 + ak[i]);
#pragma unroll
        for (int i = 0; i < 2; i++)
            cp_async16(smem_u32(&Vs[buf][bd[i]][bk[i]]),
                       Vh + (long)bd[i] * T_LEN + s0 + bk[i]);
    };

    prefetch(0, 0); cp_commit();
    prefetch(1, 1); cp_commit();
    prefetch(2, 2); cp_commit();
    cp_wait<2>();
    __syncthreads();

    uint32_t aAddr[3][2], bAddr[3][2];
#pragma unroll
    for (int st = 0; st < 3; st++) {
#pragma unroll
        for (int i = 0; i < 2; i++)
            aAddr[st][i] = smem_u32(
                &Ps[st][wm0 + i*16 + (lane & 15)][(lane >> 4) * 8]);
#pragma unroll
        for (int jp = 0; jp < 2; jp++)
            bAddr[st][jp] = smem_u32(
                &Vs[st][wn0 + jp*16 + (lane & 7) + ((lane >> 4) << 3)]
                       [((lane >> 3) & 1) * 8]);
    }

    float acc[2][4][4];
#pragma unroll
    for (int i = 0; i < 2; i++)
#pragma unroll
        for (int j = 0; j < 4; j++)
#pragma unroll
            for (int q = 0; q < 4; q++) acc[i][j][q] = 0.0f;

#pragma unroll 1
    for (int it = 0; it < CTX_NI; ++it) {
        const int buf = it % 3;
#pragma unroll
        for (int ks = 0; ks < 4; ks++) {
            uint32_t af[2][4], bq[2][4];
#pragma unroll
            for (int i = 0; i < 2; i++) ldsm_x4(af[i], aAddr[buf][i] + ks * 32);
#pragma unroll
            for (int jp = 0; jp < 2; jp++) ldsm_x4(bq[jp], bAddr[buf][jp] + ks * 32);
#pragma unroll
            for (int i = 0; i < 2; i++)
#pragma unroll
                for (int j = 0; j < 4; j++)
                    mma_f16(acc[i][j], af[i][0], af[i][1], af[i][2], af[i][3],
                            bq[j >> 1][(j & 1) * 2], bq[j >> 1][(j & 1) * 2 + 1]);
        }
        __syncthreads();
        if (it + 3 < CTX_NI) { prefetch(it + 3, buf); cp_commit(); }
        if (it + 1 < CTX_NI) {
            if (it + 3 < CTX_NI)       cp_wait<2>();
            else if (it + 2 < CTX_NI)  cp_wait<1>();
            else                       cp_wait<0>();
            __syncthreads();
        }
    }

    const float* invh = inv + (long)h * T_LEN;
#pragma unroll
    for (int i = 0; i < 2; i++) {
#pragma unroll
        for (int j = 0; j < 4; j++) {
#pragma unroll
            for (int h2 = 0; h2 < 2; h2++) {
                const int m = gm0 + wm0 + i*16 + gid + h2*8;
                const int n = h * HD + wn0 + j*8 + tg*2;
                const float sc = invh[m];
                float v0 = acc[i][j][h2*2 + 0] * sc;
                float v1 = acc[i][j][h2*2 + 1] * sc;
                *(__half2*)(CTX + (long)m * E_DIM + n) = __floats2half2_rn(v0, v1);
            }
        }
    }
}

// ===========================================================================
// Merged QKV projection GEMM (unchanged).
// ===========================================================================
__global__ __launch_bounds__(256, 2)
void qkv_k(const __half* __restrict__ X16, const __half* __restrict__ W16,
           const float* __restrict__ bias3,
           __half* __restrict__ Q, __half* __restrict__ Kq,
           __half* __restrict__ Vt)
{
    constexpr int BK = 32;
    constexpr int KD = E_DIM;
    __shared__ __half As[3][128][40];
    __shared__ __half Bs[3][128][40];
    constexpr uint32_t A_BUF = 128 * 40 * 2;
    constexpr uint32_t B_BUF = 128 * 40 * 2;

    const int z = blockIdx.z;
    const __half* A = X16 + (long)z * T_LEN * E_DIM;
    const __half* B = W16 + (long)z * E_DIM * E_DIM;
    const float* bias = bias3 + z * E_DIM;
    __half* C = (z == 0) ? Q : (z == 1) ? Kq : Vt;
    const float scale = (z == 0) ? 0.125f : 1.0f;

    const int tid  = threadIdx.x;
    const int warp = tid >> 5, lane = tid & 31;
    const int wm0 = (warp >> 2) * 64;
    const int wn0 = (warp & 3) * 32;
    const int gid = lane >> 2, tg = lane & 3;
    const int gm0 = blockIdx.y * 128, gn0 = blockIdx.x * 128;

    int am[2], ak[2];
#pragma unroll
    for (int i = 0; i < 2; i++) {
        const int idx = (tid + i * 256) * 8;
        am[i] = idx >> 5; ak[i] = idx & 31;
    }

    auto prefetch = [&](int it, int buf) {
        const int k0 = it * BK;
#pragma unroll
        for (int i = 0; i < 2; i++)
            cp_async16(smem_u32(&As[buf][am[i]][ak[i]]),
                       A + (long)(gm0 + am[i]) * KD + k0 + ak[i]);
#pragma unroll
        for (int i = 0; i < 2; i++)
            cp_async16(smem_u32(&Bs[buf][am[i]][ak[i]]),
                       B + (long)(gn0 + am[i]) * KD + k0 + ak[i]);
    };

    const int NI = KD / BK;
    prefetch(0, 0); cp_commit();
    prefetch(1, 1); cp_commit();
    prefetch(2, 2); cp_commit();
    cp_wait<2>();
    __syncthreads();

    uint32_t aAddr0[4], bAddr0[2];
#pragma unroll
    for (int i = 0; i < 4; i++)
        aAddr0[i] = smem_u32(&As[0][wm0 + i*16 + (lane & 15)][(lane >> 4) * 8]);
#pragma unroll
    for (int jp = 0; jp < 2; jp++)
        bAddr0[jp] = smem_u32(&Bs[0][wn0 + jp*16 + (lane & 7) + ((lane >> 4) << 3)]
                                 [((lane >> 3) & 1) * 8]);

    float acc[4][4][4];
#pragma unroll
    for (int i = 0; i < 4; i++)
#pragma unroll
        for (int j = 0; j < 4; j++)
#pragma unroll
            for (int q = 0; q < 4; q++) acc[i][j][q] = 0.0f;

#pragma unroll 1
    for (int it = 0; it < NI; ++it) {
        const int buf = it % 3;
        const uint32_t aB = buf * A_BUF, bB = buf * B_BUF;
#pragma unroll
        for (int ks = 0; ks < BK; ks += 16) {
            uint32_t af[4][4], bq[2][4];
#pragma unroll
            for (int i = 0; i < 4; i++) ldsm_x4(af[i], aAddr0[i] + aB + ks * 2);
#pragma unroll
            for (int jp = 0; jp < 2; jp++) ldsm_x4(bq[jp], bAddr0[jp] + bB + ks * 2);
#pragma unroll
            for (int i = 0; i < 4; i++)
#pragma unroll
                for (int j = 0; j < 4; j++)
                    mma_f16(acc[i][j], af[i][0], af[i][1], af[i][2], af[i][3],
                            bq[j >> 1][(j & 1) * 2], bq[j >> 1][(j & 1) * 2 + 1]);
        }
        __syncthreads();
        if (it + 3 < NI) { prefetch(it + 3, buf); cp_commit(); }
        if (it + 1 < NI) {
            if (it + 3 < NI)       cp_wait<2>();
            else if (it + 2 < NI)  cp_wait<1>();
            else                   cp_wait<0>();
            __syncthreads();
        }
    }

#pragma unroll
    for (int i = 0; i < 4; i++) {
#pragma unroll
        for (int j = 0; j < 4; j++) {
#pragma unroll
            for (int h2 = 0; h2 < 2; h2++) {
                int m = gm0 + wm0 + i*16 + gid + h2*8;
                int n = gn0 + wn0 + j*8 + tg*2;
                float v0 = (acc[i][j][h2*2 + 0] + bias[n])   * scale;
                float v1 = (acc[i][j][h2*2 + 1] + bias[n+1]) * scale;
                int h = n >> 6, d = n & 63;
                if (z < 2) {
                    *(__half2*)(C + (long)h*T_LEN*HD + (long)m*HD + d) =
                        __floats2half2_rn(v0, v1);
                } else {
                    __half* p = C + (long)h*HD*T_LEN + (long)d*T_LEN + m;
                    p[0]     = __float2half_rn(v0);
                    p[T_LEN] = __float2half_rn(v1);
                }
            }
        }
    }
}

// ===========================================================================
// Out-projection GEMM (unchanged).
// ===========================================================================
__global__ __launch_bounds__(256, 2)
void outproj_k(const __half* __restrict__ A, const __half* __restrict__ B,
               const float* __restrict__ bias, float* __restrict__ C)
{
    constexpr int BK = 32;
    constexpr int KD = E_DIM;
    __shared__ __half As[3][128][40];
    __shared__ __half Bs[3][128][40];
    constexpr uint32_t A_BUF = 128 * 40 * 2;
    constexpr uint32_t B_BUF = 128 * 40 * 2;

    const int tid  = threadIdx.x;
    const int warp = tid >> 5, lane = tid & 31;
    const int wm0 = (warp >> 2) * 64;
    const int wn0 = (warp & 3) * 32;
    const int gid = lane >> 2, tg = lane & 3;
    const int gm0 = blockIdx.y * 128, gn0 = blockIdx.x * 128;

    int am[2], ak[2];
#pragma unroll
    for (int i = 0; i < 2; i++) {
        const int idx = (tid + i * 256) * 8;
        am[i] = idx >> 5; ak[i] = idx & 31;
    }

    auto prefetch = [&](int it, int buf) {
        const int k0 = it * BK;
#pragma unroll
        for (int i = 0; i < 2; i++)
            cp_async16(smem_u32(&As[buf][am[i]][ak[i]]),
                       A + (long)(gm0 + am[i]) * KD + k0 + ak[i]);
#pragma unroll
        for (int i = 0; i < 2; i++)
            cp_async16(smem_u32(&Bs[buf][am[i]][ak[i]]),
                       B + (long)(gn0 + am[i]) * KD + k0 + ak[i]);
    };

    const int NI = KD / BK;
    prefetch(0, 0); cp_commit();
    prefetch(1, 1); cp_commit();
    prefetch(2, 2); cp_commit();
    cp_wait<2>();
    __syncthreads();

    uint32_t aAddr0[4], bAddr0[2];
#pragma unroll
    for (int i = 0; i < 4; i++)
        aAddr0[i] = smem_u32(&As[0][wm0 + i*16 + (lane & 15)][(lane >> 4) * 8]);
#pragma unroll
    for (int jp = 0; jp < 2; jp++)
        bAddr0[jp] = smem_u32(&Bs[0][wn0 + jp*16 + (lane & 7) + ((lane >> 4) << 3)]
                                 [((lane >> 3) & 1) * 8]);

    float acc[4][4][4];
#pragma unroll
    for (int i = 0; i < 4; i++)
#pragma unroll
        for (int j = 0; j < 4; j++)
#pragma unroll
            for (int q = 0; q < 4; q++) acc[i][j][q] = 0.0f;

#pragma unroll 1
    for (int it = 0; it < NI; ++it) {
        const int buf = it % 3;
        const uint32_t aB = buf * A_BUF, bB = buf * B_BUF;
#pragma unroll
        for (int ks = 0; ks < BK; ks += 16) {
            uint32_t af[4][4], bq[2][4];
#pragma unroll
            for (int i = 0; i < 4; i++) ldsm_x4(af[i], aAddr0[i] + aB + ks * 2);
#pragma unroll
            for (int jp = 0; jp < 2; jp++) ldsm_x4(bq[jp], bAddr0[jp] + bB + ks * 2);
#pragma unroll
            for (int i = 0; i < 4; i++)
#pragma unroll
                for (int j = 0; j < 4; j++)
                    mma_f16(acc[i][j], af[i][0], af[i][1], af[i][2], af[i][3],
                            bq[j >> 1][(j & 1) * 2], bq[j >> 1][(j & 1) * 2 + 1]);
        }
        __syncthreads();
        if (it + 3 < NI) { prefetch(it + 3, buf); cp_commit(); }
        if (it + 1 < NI) {
            if (it + 3 < NI)       cp_wait<2>();
            else if (it + 2 < NI)  cp_wait<1>();
            else                   cp_wait<0>();
            __syncthreads();
        }
    }

#pragma unroll
    for (int i = 0; i < 4; i++) {
#pragma unroll
        for (int j = 0; j < 4; j++) {
#pragma unroll
            for (int h2 = 0; h2 < 2; h2++) {
                int m = gm0 + wm0 + i*16 + gid + h2*8;
                int n = gn0 + wn0 + j*8 + tg*2;
                float v0 = acc[i][j][h2*2 + 0] + bias[n];
                float v1 = acc[i][j][h2*2 + 1] + bias[n+1];
                *(float2*)(C + (long)m*E_DIM + n) = make_float2(v0, v1);
            }
        }
    }
}

// ---------------------------------------------------------------------------
__global__ __launch_bounds__(256) void invred_k(const float* __restrict__ part,
                                                float* __restrict__ inv)
{
    const long row = (long)blockIdx.x * 256 + threadIdx.x;
    const float4 p = ((const float4*)part)[row];
    inv[row] = 1.0f / ((p.x + p.y) + (p.z + p.w));
}

// ---------------------------------------------------------------------------
__global__ __launch_bounds__(1024) void avg_k(const __half* __restrict__ P,
                                              const float* __restrict__ inv,
                                              float* __restrict__ out)
{
    const int t = blockIdx.x, tid = threadIdx.x;
    const long TS = (long)T_LEN * T_LEN;
    const __half* base = P + (long)t * T_LEN + tid * 4;
    float4 acc = make_float4(0.f, 0.f, 0.f, 0.f);
#pragma unroll
    for (int h = 0; h < H_NUM; h++) {
        const float iv = inv[h * T_LEN + t] * (1.0f / H_NUM);
        uint2 u = *(const uint2*)(base + (long)h * TS);
        float2 lo = __half22float2(*(__half2*)&u.x);
        float2 hi = __half22float2(*(__half2*)&u.y);
        acc.x += lo.x * iv; acc.y += lo.y * iv;
        acc.z += hi.x * iv; acc.w += hi.y * iv;
    }
    ((float4*)(out + (long)t * T_LEN))[tid] = acc;
}

// ---------------------------------------------------------------------------
extern "C" void kernel_launch(void* const* d_in, const int* in_sizes, int n_in,
                              void* d_out, int out_size)
{
    const float* q_in = (const float*)d_in[0];
    const float* k_in = (const float*)d_in[1];
    const float* v_in = (const float*)d_in[2];
    const float* w    = (const float*)d_in[3];
    const float* b    = (const float*)d_in[4];
    const float* ow   = (const float*)d_in[5];
    const float* ob   = (const float*)d_in[6];
    float* out = (float*)d_out;

    __half *Q, *K, *Vt, *P, *CTX, *X16, *W16;
    float *RSP, *INV;
    cudaGetSymbolAddress((void**)&Q,   g_Q);
    cudaGetSymbolAddress((void**)&K,   g_K);
    cudaGetSymbolAddress((void**)&Vt,  g_Vt);
    cudaGetSymbolAddress((void**)&P,   g_P);
    cudaGetSymbolAddress((void**)&CTX, g_CTX);
    cudaGetSymbolAddress((void**)&X16, g_X16);
    cudaGetSymbolAddress((void**)&W16, g_W16);
    cudaGetSymbolAddress((void**)&RSP, g_RSP);
    cudaGetSymbolAddress((void**)&INV, g_INV);

    const int T = T_LEN, E = E_DIM, H = H_NUM;
    const long EE = (long)E * E;
    dim3 blk(256);

    // second stream + fork/join events (created per call: deterministic,
    // capture-legal, not device allocations)
    cudaStream_t s1;
    cudaStreamCreateWithFlags(&s1, cudaStreamNonBlocking);
    cudaEvent_t eFork, eJoin;
    cudaEventCreateWithFlags(&eFork, cudaEventDisableTiming);
    cudaEventCreateWithFlags(&eJoin, cudaEventDisableTiming);

    // serial chain on the capture (legacy) stream
    cvt_all_k<<<16384, 256>>>(q_in, k_in, v_in, w, ow, X16, W16);
    qkv_k<<<dim3(E/128, T/128, 3), blk>>>(X16, W16, b, Q, K, Vt);
    scores_k<<<dim3(NBX_SCORES, T/128, H), blk>>>(Q, K, P, RSP);
    invred_k<<<(H*T)/256, 256>>>(RSP, INV);

    // fork: avg on s1, concurrent with ctx -> outproj on stream 0
    cudaEventRecord(eFork, 0);
    cudaStreamWaitEvent(s1, eFork, 0);
    avg_k<<<T, 1024, 0, s1>>>(P, INV, out + (long)T * E);
    cudaEventRecord(eJoin, s1);

    ctx_k<<<dim3(T/128, H), blk>>>(P, Vt, INV, CTX);
    outproj_k<<<dim3(E/128, T/128), blk>>>(CTX, W16 + 3*EE, ob, out);

    // join avg back into the capture stream
    cudaStreamWaitEvent(0, eJoin, 0);
}